// round 2
// baseline (speedup 1.0000x reference)
#include <cuda_runtime.h>

#define N_NODES 100000
#define N_FEATS 512
#define HIDDEN  64
#define NSAMP   5
#define NCLS    16
#define NBATCH  16384

typedef unsigned long long u64;

// Scratch (static device globals: allocation-free per harness rules)
__device__ float g_W1T[N_FEATS * 128];            // [512][128]
__device__ float g_W2T[HIDDEN * 128];             // [64][128]
__device__ float g_PG[(size_t)N_NODES * 128];     // P | G
__device__ float g_h1[(size_t)N_NODES * HIDDEN];
__device__ float g_UV[(size_t)N_NODES * 128];     // U | V

// ---- packed f32x2 helpers -------------------------------------------------
__device__ __forceinline__ u64 fma2(u64 a, u64 b, u64 c) {
    u64 d;
    asm("fma.rn.f32x2 %0, %1, %2, %3;" : "=l"(d) : "l"(a), "l"(b), "l"(c));
    return d;
}
__device__ __forceinline__ u64 dup2(float x) {
    u64 d;
    unsigned int xi = __float_as_uint(x);
    asm("mov.b64 %0, {%1, %1};" : "=l"(d) : "r"(xi));
    return d;
}

// ---------------------------------------------------------------------------
// Repack w1 [64,1024] and w2 [64,128] into k-major [K][128] operand matrices.
// ---------------------------------------------------------------------------
__global__ void prep_weights(const float* __restrict__ w1, const float* __restrict__ w2) {
    int idx = blockIdx.x * blockDim.x + threadIdx.x;
    if (idx < N_FEATS * 128) {
        int k = idx >> 7, n = idx & 127;
        g_W1T[idx] = (n < HIDDEN) ? w1[n * (2 * N_FEATS) + k]
                                  : w1[(n - HIDDEN) * (2 * N_FEATS) + N_FEATS + k];
    }
    if (idx < HIDDEN * 128) {
        int k = idx >> 7, n = idx & 127;
        g_W2T[idx] = (n < HIDDEN) ? w2[n * (2 * HIDDEN) + k]
                                  : w2[(n - HIDDEN) * (2 * HIDDEN) + HIDDEN + k];
    }
}

// ---------------------------------------------------------------------------
// SGEMM: C[M,128] = A[M,K] @ B[K,128]. 128x128 CTA tile, 8x8 per thread via
// packed fma.rn.f32x2 (8x4 pair-FMAs). 16-deep k-chunks, double-buffered smem
// with register staging to overlap global loads with compute.
// ---------------------------------------------------------------------------
template <int K>
__global__ __launch_bounds__(256, 2)
void gemm_n128(const float* __restrict__ A, const float* __restrict__ Bm,
               float* __restrict__ Cm, int M) {
    constexpr int KC  = 16;
    constexpr int NCH = K / KC;

    __shared__ float As[2][KC][132];   // [k][row], padded (16B-aligned rows)
    __shared__ float Bs[2][KC][132];   // [k][col], padded

    const int tid  = threadIdx.x;
    const int tx   = tid & 15;         // col group (8 cols each)
    const int ty   = tid >> 4;         // row group (8 rows each)
    const int row0 = blockIdx.x * 128;

    u64 acc[8][4];
#pragma unroll
    for (int i = 0; i < 8; i++)
#pragma unroll
        for (int j = 0; j < 4; j++) acc[i][j] = 0ull;

    float4 ra[2], rb[2];

    // precomputed load/store coordinates (2 passes of 256 threads)
    int a_r[2], a_kc[2], b_kr[2], b_nc[2];
#pragma unroll
    for (int p = 0; p < 2; p++) {
        int e   = p * 256 + tid;
        a_r[p]  = e >> 2;              // 4 float4 per 16-k row
        a_kc[p] = (e & 3) << 2;
        b_kr[p] = e >> 5;              // 32 float4 per 128-col row
        b_nc[p] = (e & 31) << 2;
    }

    auto load_regs = [&](int k0) {
#pragma unroll
        for (int p = 0; p < 2; p++) {
            int gr = row0 + a_r[p];
            ra[p] = (gr < M) ? *(const float4*)(A + (size_t)gr * K + k0 + a_kc[p])
                             : make_float4(0.f, 0.f, 0.f, 0.f);
            rb[p] = *(const float4*)(Bm + (size_t)(k0 + b_kr[p]) * 128 + b_nc[p]);
        }
    };
    auto store_smem = [&](int buf) {
#pragma unroll
        for (int p = 0; p < 2; p++) {
            As[buf][a_kc[p] + 0][a_r[p]] = ra[p].x;
            As[buf][a_kc[p] + 1][a_r[p]] = ra[p].y;
            As[buf][a_kc[p] + 2][a_r[p]] = ra[p].z;
            As[buf][a_kc[p] + 3][a_r[p]] = ra[p].w;
            *(float4*)&Bs[buf][b_kr[p]][b_nc[p]] = rb[p];
        }
    };

    load_regs(0);
    store_smem(0);
    __syncthreads();

    for (int t = 0; t < NCH; ++t) {
        int buf = t & 1;
        if (t + 1 < NCH) load_regs((t + 1) * KC);

#pragma unroll
        for (int k = 0; k < KC; k++) {
            float4 a0 = *(const float4*)&As[buf][k][ty * 8];
            float4 a1 = *(const float4*)&As[buf][k][ty * 8 + 4];
            ulonglong2 b01 = *(const ulonglong2*)&Bs[buf][k][tx * 8];
            ulonglong2 b23 = *(const ulonglong2*)&Bs[buf][k][tx * 8 + 4];
            u64 aa[8];
            aa[0] = dup2(a0.x); aa[1] = dup2(a0.y);
            aa[2] = dup2(a0.z); aa[3] = dup2(a0.w);
            aa[4] = dup2(a1.x); aa[5] = dup2(a1.y);
            aa[6] = dup2(a1.z); aa[7] = dup2(a1.w);
#pragma unroll
            for (int i = 0; i < 8; i++) {
                acc[i][0] = fma2(aa[i], b01.x, acc[i][0]);
                acc[i][1] = fma2(aa[i], b01.y, acc[i][1]);
                acc[i][2] = fma2(aa[i], b23.x, acc[i][2]);
                acc[i][3] = fma2(aa[i], b23.y, acc[i][3]);
            }
        }

        if (t + 1 < NCH) store_smem(buf ^ 1);
        __syncthreads();
    }

#pragma unroll
    for (int i = 0; i < 8; i++) {
        int gr = row0 + ty * 8 + i;
        if (gr < M) {
            *(ulonglong2*)(Cm + (size_t)gr * 128 + tx * 8) =
                make_ulonglong2(acc[i][0], acc[i][1]);
            *(ulonglong2*)(Cm + (size_t)gr * 128 + tx * 8 + 4) =
                make_ulonglong2(acc[i][2], acc[i][3]);
        }
    }
}

// ---------------------------------------------------------------------------
// Layer-1 aggregation in 64-dim space:
//   h1[n] = relu(P[n] + 0.2 * sum_s G[neigh[n,s]])
// ---------------------------------------------------------------------------
__global__ void aggregate1_kernel(const int* __restrict__ neigh) {
    int gw   = (blockIdx.x * 256 + threadIdx.x) >> 5;
    int lane = threadIdx.x & 31;
    if (gw >= N_NODES) return;

    const float* base = g_PG + (size_t)gw * 128;
    float2 s = *(const float2*)(base + lane * 2);
    float ax = 0.f, ay = 0.f;
#pragma unroll
    for (int j = 0; j < NSAMP; j++) {
        int nb = __ldg(&neigh[gw * NSAMP + j]);
        float2 v = *(const float2*)(g_PG + (size_t)nb * 128 + 64 + lane * 2);
        ax += v.x; ay += v.y;
    }
    float hx = fmaxf(fmaf(ax, 0.2f, s.x), 0.f);
    float hy = fmaxf(fmaf(ay, 0.2f, s.y), 0.f);
    *(float2*)(g_h1 + (size_t)gw * 64 + lane * 2) = make_float2(hx, hy);
}

// ---------------------------------------------------------------------------
// Final: h2 = relu(U[n] + 0.2 * sum_s V[neigh[n,s]]); out = h2 @ w_cls.T
// ---------------------------------------------------------------------------
__global__ __launch_bounds__(256)
void final_kernel(const int* __restrict__ nodes, const int* __restrict__ neigh,
                  const float* __restrict__ wcls, float* __restrict__ out) {
    __shared__ float h2s[4][64];
    __shared__ float wcs[16][66];

    int tid = threadIdx.x;
    for (int i = tid; i < NCLS * HIDDEN; i += 256)
        wcs[i >> 6][i & 63] = wcls[i];

    int sub = tid >> 6;
    int h   = tid & 63;
    int b   = blockIdx.x * 4 + sub;

    float val = 0.f;
    if (b < NBATCH) {
        int n = nodes[b];
        float self = g_UV[(size_t)n * 128 + h];
        float acc = 0.f;
#pragma unroll
        for (int j = 0; j < NSAMP; j++) {
            int nb = __ldg(&neigh[n * NSAMP + j]);
            acc += g_UV[(size_t)nb * 128 + 64 + h];
        }
        val = fmaxf(fmaf(acc, 0.2f, self), 0.f);
    }
    h2s[sub][h] = val;
    __syncthreads();

    if (tid < 64) {
        int sub2 = tid >> 4;
        int c    = tid & 15;
        int b2   = blockIdx.x * 4 + sub2;
        if (b2 < NBATCH) {
            float acc = 0.f;
#pragma unroll
            for (int k = 0; k < HIDDEN; k++)
                acc = fmaf(wcs[c][k], h2s[sub2][k], acc);
            out[b2 * NCLS + c] = acc;
        }
    }
}

// ---------------------------------------------------------------------------
extern "C" void kernel_launch(void* const* d_in, const int* in_sizes, int n_in,
                              void* d_out, int out_size) {
    const float* features = (const float*)d_in[0];
    const float* w1       = (const float*)d_in[1];
    const float* w2       = (const float*)d_in[2];
    const float* wcls     = (const float*)d_in[3];
    const int*   nodes    = (const int*)d_in[4];
    const int*   neigh    = (const int*)d_in[5];
    float*       out      = (float*)d_out;

    float *pW1T, *pW2T, *pPG, *ph1, *pUV;
    cudaGetSymbolAddress((void**)&pW1T, g_W1T);
    cudaGetSymbolAddress((void**)&pW2T, g_W2T);
    cudaGetSymbolAddress((void**)&pPG,  g_PG);
    cudaGetSymbolAddress((void**)&ph1,  g_h1);
    cudaGetSymbolAddress((void**)&pUV,  g_UV);

    const int gemm_blocks = (N_NODES + 127) / 128;   // 782

    prep_weights<<<(N_FEATS * 128 + 255) / 256, 256>>>(w1, w2);
    gemm_n128<N_FEATS><<<gemm_blocks, 256>>>(features, pW1T, pPG, N_NODES);
    aggregate1_kernel<<<(N_NODES * 32 + 255) / 256, 256>>>(neigh);
    gemm_n128<HIDDEN><<<gemm_blocks, 256>>>(ph1, pW2T, pUV, N_NODES);
    final_kernel<<<(NBATCH + 3) / 4, 256>>>(nodes, neigh, wcls, out);
}

// round 4
// speedup vs baseline: 1.5939x; 1.5939x over previous
#include <cuda_runtime.h>
#include <cuda_bf16.h>

#define N_NODES 100000
#define N_FEATS 512
#define HIDDEN  64
#define NSAMP   5
#define NCLS    16
#define NBATCH  16384

typedef unsigned int u32;

// ---------------- scratch (static device globals) ---------------------------
__device__ __nv_bfloat16 g_W1h[128 * N_FEATS];   // [n=0..127][k] row-major
__device__ __nv_bfloat16 g_W1l[128 * N_FEATS];
__device__ __nv_bfloat16 g_W2h[128 * HIDDEN];
__device__ __nv_bfloat16 g_W2l[128 * HIDDEN];
__device__ __nv_bfloat16 g_h1h[(size_t)N_NODES * HIDDEN];
__device__ __nv_bfloat16 g_h1l[(size_t)N_NODES * HIDDEN];
__device__ float g_PG[(size_t)N_NODES * 128];    // P | G  (layer-1 pre-act)
__device__ float g_UV[(size_t)N_NODES * 128];    // U | V  (layer-2 pre-act)

// ---------------- helpers ----------------------------------------------------
__device__ __forceinline__ u32 smem_u32(const void* p) {
    u32 a;
    asm("{ .reg .u64 t; cvta.to.shared.u64 t, %1; cvt.u32.u64 %0, t; }"
        : "=r"(a) : "l"(p));
    return a;
}
__device__ __forceinline__ void ldsm4(u32& r0, u32& r1, u32& r2, u32& r3, u32 addr) {
    asm volatile("ldmatrix.sync.aligned.m8n8.x4.shared.b16 {%0,%1,%2,%3}, [%4];"
                 : "=r"(r0), "=r"(r1), "=r"(r2), "=r"(r3) : "r"(addr));
}
__device__ __forceinline__ void mma_bf16(float* d, const u32* a, const u32* b) {
    asm volatile(
        "mma.sync.aligned.m16n8k16.row.col.f32.bf16.bf16.f32 "
        "{%0,%1,%2,%3}, {%4,%5,%6,%7}, {%8,%9}, {%0,%1,%2,%3};"
        : "+f"(d[0]), "+f"(d[1]), "+f"(d[2]), "+f"(d[3])
        : "r"(a[0]), "r"(a[1]), "r"(a[2]), "r"(a[3]), "r"(b[0]), "r"(b[1]));
}
#define SW128(x) ((x) ^ (((x) >> 3) & 0x70))

// smem tile offsets (bytes): 4 tiles of 128 rows x 128B (KC=64 bf16)
#define SA_H 0
#define SA_L 16384
#define SB_H 32768
#define SB_L 49152
#define SMEM_BYTES 65536

// ---------------------------------------------------------------------------
// Weight prep: split fp32 weights into bf16 hi/lo, [n=0..127][k] row-major
// (n<64 -> self block, n>=64 -> neighbor block).
// ---------------------------------------------------------------------------
__global__ void prep_weights(const float* __restrict__ w1, const float* __restrict__ w2) {
    int idx = blockIdx.x * 256 + threadIdx.x;
    if (idx < 128 * N_FEATS) {
        int n = idx / N_FEATS, k = idx % N_FEATS;
        float v = (n < 64) ? w1[n * (2 * N_FEATS) + k]
                           : w1[(n - 64) * (2 * N_FEATS) + N_FEATS + k];
        __nv_bfloat16 h = __float2bfloat16(v);
        g_W1h[idx] = h;
        g_W1l[idx] = __float2bfloat16(v - __bfloat162float(h));
    }
    if (idx < 128 * HIDDEN) {
        int n = idx / HIDDEN, k = idx % HIDDEN;
        float v = (n < 64) ? w2[n * (2 * HIDDEN) + k]
                           : w2[(n - 64) * (2 * HIDDEN) + HIDDEN + k];
        __nv_bfloat16 h = __float2bfloat16(v);
        g_W2h[idx] = h;
        g_W2l[idx] = __float2bfloat16(v - __bfloat162float(h));
    }
}

// ---------------------------------------------------------------------------
// Split-bf16 HMMA GEMM: C[M,128] = A[M,K] @ B[128,K]^T, fp32 accumulate.
// 128x128 CTA tile, 8 warps (warp tile 64x32), KC=64, SW128 smem,
// register-staged global loads overlapping MMA compute.
// ---------------------------------------------------------------------------
template <int K, bool AFP32>
__global__ __launch_bounds__(256)
void gemm_mma(const float* __restrict__ Af,
              const __nv_bfloat16* __restrict__ Ah,
              const __nv_bfloat16* __restrict__ Al,
              const __nv_bfloat16* __restrict__ Bh,
              const __nv_bfloat16* __restrict__ Bl,
              float* __restrict__ Cm, int M) {
    constexpr int KC = 64;
    constexpr int NCH = K / KC;

    extern __shared__ __align__(1024) char smem[];
    const u32 sb = smem_u32(smem);
    const int tid  = threadIdx.x;
    const int wid  = tid >> 5;
    const int lane = tid & 31;
    const int wm   = (wid & 1) * 64;       // warp M offset within tile
    const int wn   = (wid >> 1) * 32;      // warp N offset within tile
    const int row0 = blockIdx.x * 128;

    // ---- loader coords: each thread owns half a 128B row of each tile ----
    const int lrow  = tid >> 1;            // 0..127
    const int lhalf = (tid & 1) * 32;      // k element offset
    const bool arow_ok = (row0 + lrow) < M;

    uint4 ahr[4], alr[4], bhr[4], blr[4];

    auto loadA = [&](int k0) {
        if constexpr (AFP32) {
            const float* src = Af + (size_t)(row0 + lrow) * K + k0 + lhalf;
#pragma unroll
            for (int j = 0; j < 4; j++) {
                float f[8];
                if (arow_ok) {
                    float4 v0 = *(const float4*)(src + j * 8);
                    float4 v1 = *(const float4*)(src + j * 8 + 4);
                    f[0]=v0.x; f[1]=v0.y; f[2]=v0.z; f[3]=v0.w;
                    f[4]=v1.x; f[5]=v1.y; f[6]=v1.z; f[7]=v1.w;
                } else {
#pragma unroll
                    for (int e = 0; e < 8; e++) f[e] = 0.f;
                }
                u32 hh[8], ll[8];
#pragma unroll
                for (int e = 0; e < 8; e++) {
                    __nv_bfloat16 h = __float2bfloat16(f[e]);
                    __nv_bfloat16 l = __float2bfloat16(f[e] - __bfloat162float(h));
                    hh[e] = *(unsigned short*)&h;
                    ll[e] = *(unsigned short*)&l;
                }
                ahr[j] = make_uint4(hh[0] | (hh[1] << 16), hh[2] | (hh[3] << 16),
                                    hh[4] | (hh[5] << 16), hh[6] | (hh[7] << 16));
                alr[j] = make_uint4(ll[0] | (ll[1] << 16), ll[2] | (ll[3] << 16),
                                    ll[4] | (ll[5] << 16), ll[6] | (ll[7] << 16));
            }
        } else {
            const __nv_bfloat16* sh = Ah + (size_t)(row0 + lrow) * K + k0 + lhalf;
            const __nv_bfloat16* sl = Al + (size_t)(row0 + lrow) * K + k0 + lhalf;
#pragma unroll
            for (int j = 0; j < 4; j++) {
                ahr[j] = arow_ok ? *(const uint4*)(sh + j * 8) : make_uint4(0, 0, 0, 0);
                alr[j] = arow_ok ? *(const uint4*)(sl + j * 8) : make_uint4(0, 0, 0, 0);
            }
        }
    };
    auto loadB = [&](int k0) {
        const __nv_bfloat16* sh = Bh + (size_t)lrow * K + k0 + lhalf;
        const __nv_bfloat16* sl = Bl + (size_t)lrow * K + k0 + lhalf;
#pragma unroll
        for (int j = 0; j < 4; j++) {
            bhr[j] = *(const uint4*)(sh + j * 8);
            blr[j] = *(const uint4*)(sl + j * 8);
        }
    };
    auto sts = [&]() {
        const u32 rowoff = lrow * 128 + lhalf * 2;
#pragma unroll
        for (int j = 0; j < 4; j++) {
            u32 off = SW128(rowoff + j * 16);
            *(uint4*)(smem + SA_H + off) = ahr[j];
            *(uint4*)(smem + SA_L + off) = alr[j];
            *(uint4*)(smem + SB_H + off) = bhr[j];
            *(uint4*)(smem + SB_L + off) = blr[j];
        }
    };

    // ---- ldmatrix lane coords ----
    const int grp = lane >> 3, lr = lane & 7;
    const int a_m  = wm + (grp & 1) * 8 + lr;     // + mt*16
    const int a_kb = (grp >> 1) * 16;             // + ks*32  (bytes)
    const int b_n  = wn + (grp >> 1) * 8 + lr;    // + p*16
    const int b_kb = (grp & 1) * 16;              // + ks*32  (bytes)

    float acc[4][4][4];
#pragma unroll
    for (int i = 0; i < 4; i++)
#pragma unroll
        for (int j = 0; j < 4; j++)
#pragma unroll
            for (int c = 0; c < 4; c++) acc[i][j][c] = 0.f;

    loadA(0); loadB(0);
    sts();
    __syncthreads();

    for (int t = 0; t < NCH; ++t) {
        if (t + 1 < NCH) { loadA((t + 1) * KC); loadB((t + 1) * KC); }

#pragma unroll
        for (int ks = 0; ks < 4; ks++) {
            u32 ah4[4][4], al4[4][4];
#pragma unroll
            for (int mt = 0; mt < 4; mt++) {
                u32 off = SW128((u32)((a_m + mt * 16) * 128 + ks * 32 + a_kb));
                ldsm4(ah4[mt][0], ah4[mt][1], ah4[mt][2], ah4[mt][3], sb + SA_H + off);
                ldsm4(al4[mt][0], al4[mt][1], al4[mt][2], al4[mt][3], sb + SA_L + off);
            }
            u32 bh4[4][2], bl4[4][2];
#pragma unroll
            for (int p = 0; p < 2; p++) {
                u32 off = SW128((u32)((b_n + p * 16) * 128 + ks * 32 + b_kb));
                u32 r0, r1, r2, r3;
                ldsm4(r0, r1, r2, r3, sb + SB_H + off);
                bh4[2 * p][0] = r0; bh4[2 * p][1] = r1;
                bh4[2 * p + 1][0] = r2; bh4[2 * p + 1][1] = r3;
                ldsm4(r0, r1, r2, r3, sb + SB_L + off);
                bl4[2 * p][0] = r0; bl4[2 * p][1] = r1;
                bl4[2 * p + 1][0] = r2; bl4[2 * p + 1][1] = r3;
            }
#pragma unroll
            for (int mt = 0; mt < 4; mt++)
#pragma unroll
                for (int nt = 0; nt < 4; nt++) {
                    mma_bf16(acc[mt][nt], ah4[mt], bh4[nt]);
                    mma_bf16(acc[mt][nt], ah4[mt], bl4[nt]);
                    mma_bf16(acc[mt][nt], al4[mt], bh4[nt]);
                }
        }

        if (t + 1 < NCH) {
            __syncthreads();
            sts();
            __syncthreads();
        }
    }

    // ---- epilogue: fragment -> global fp32 ----
    const int tm = lane >> 2;
    const int tn = (lane & 3) * 2;
#pragma unroll
    for (int mt = 0; mt < 4; mt++) {
        int gm0 = row0 + wm + mt * 16 + tm;
#pragma unroll
        for (int nt = 0; nt < 4; nt++) {
            int gn = wn + nt * 8 + tn;
            if (gm0 < M)
                *(float2*)(Cm + (size_t)gm0 * 128 + gn) =
                    make_float2(acc[mt][nt][0], acc[mt][nt][1]);
            if (gm0 + 8 < M)
                *(float2*)(Cm + (size_t)(gm0 + 8) * 128 + gn) =
                    make_float2(acc[mt][nt][2], acc[mt][nt][3]);
        }
    }
}

// ---------------------------------------------------------------------------
// Layer-1 aggregation in 64-dim space, emitting h1 as bf16 hi/lo:
//   h1[n] = relu(P[n] + 0.2 * sum_s G[neigh[n,s]])
// ---------------------------------------------------------------------------
__global__ void aggregate1_kernel(const int* __restrict__ neigh) {
    int gw   = (blockIdx.x * 256 + threadIdx.x) >> 5;
    int lane = threadIdx.x & 31;
    if (gw >= N_NODES) return;

    const float* base = g_PG + (size_t)gw * 128;
    float2 s = *(const float2*)(base + lane * 2);
    float ax = 0.f, ay = 0.f;
#pragma unroll
    for (int j = 0; j < NSAMP; j++) {
        int nb = __ldg(&neigh[gw * NSAMP + j]);
        float2 v = *(const float2*)(g_PG + (size_t)nb * 128 + 64 + lane * 2);
        ax += v.x; ay += v.y;
    }
    float hx = fmaxf(fmaf(ax, 0.2f, s.x), 0.f);
    float hy = fmaxf(fmaf(ay, 0.2f, s.y), 0.f);

    __nv_bfloat16 xh = __float2bfloat16(hx);
    __nv_bfloat16 xl = __float2bfloat16(hx - __bfloat162float(xh));
    __nv_bfloat16 yh = __float2bfloat16(hy);
    __nv_bfloat16 yl = __float2bfloat16(hy - __bfloat162float(yh));
    *(__nv_bfloat162*)(g_h1h + (size_t)gw * 64 + lane * 2) = __halves2bfloat162(xh, yh);
    *(__nv_bfloat162*)(g_h1l + (size_t)gw * 64 + lane * 2) = __halves2bfloat162(xl, yl);
}

// ---------------------------------------------------------------------------
// Final: h2 = relu(U[n] + 0.2 * sum_s V[neigh[n,s]]); out = h2 @ w_cls.T
// ---------------------------------------------------------------------------
__global__ __launch_bounds__(256)
void final_kernel(const int* __restrict__ nodes, const int* __restrict__ neigh,
                  const float* __restrict__ wcls, float* __restrict__ out) {
    __shared__ float h2s[4][64];
    __shared__ float wcs[16][66];

    int tid = threadIdx.x;
    for (int i = tid; i < NCLS * HIDDEN; i += 256)
        wcs[i >> 6][i & 63] = wcls[i];

    int sub = tid >> 6;
    int h   = tid & 63;
    int b   = blockIdx.x * 4 + sub;

    float val = 0.f;
    if (b < NBATCH) {
        int n = nodes[b];
        float self = g_UV[(size_t)n * 128 + h];
        float acc = 0.f;
#pragma unroll
        for (int j = 0; j < NSAMP; j++) {
            int nb = __ldg(&neigh[n * NSAMP + j]);
            acc += g_UV[(size_t)nb * 128 + 64 + h];
        }
        val = fmaxf(fmaf(acc, 0.2f, self), 0.f);
    }
    h2s[sub][h] = val;
    __syncthreads();

    if (tid < 64) {
        int sub2 = tid >> 4;
        int c    = tid & 15;
        int b2   = blockIdx.x * 4 + sub2;
        if (b2 < NBATCH) {
            float acc = 0.f;
#pragma unroll
            for (int k = 0; k < HIDDEN; k++)
                acc = fmaf(wcs[c][k], h2s[sub2][k], acc);
            out[b2 * NCLS + c] = acc;
        }
    }
}

// ---------------------------------------------------------------------------
extern "C" void kernel_launch(void* const* d_in, const int* in_sizes, int n_in,
                              void* d_out, int out_size) {
    const float* features = (const float*)d_in[0];
    const float* w1       = (const float*)d_in[1];
    const float* w2       = (const float*)d_in[2];
    const float* wcls     = (const float*)d_in[3];
    const int*   nodes    = (const int*)d_in[4];
    const int*   neigh    = (const int*)d_in[5];
    float*       out      = (float*)d_out;

    __nv_bfloat16 *pW1h, *pW1l, *pW2h, *pW2l, *ph1h, *ph1l;
    float *pPG, *pUV;
    cudaGetSymbolAddress((void**)&pW1h, g_W1h);
    cudaGetSymbolAddress((void**)&pW1l, g_W1l);
    cudaGetSymbolAddress((void**)&pW2h, g_W2h);
    cudaGetSymbolAddress((void**)&pW2l, g_W2l);
    cudaGetSymbolAddress((void**)&ph1h, g_h1h);
    cudaGetSymbolAddress((void**)&ph1l, g_h1l);
    cudaGetSymbolAddress((void**)&pPG,  g_PG);
    cudaGetSymbolAddress((void**)&pUV,  g_UV);

    cudaFuncSetAttribute(gemm_mma<N_FEATS, true>,
                         cudaFuncAttributeMaxDynamicSharedMemorySize, SMEM_BYTES);
    cudaFuncSetAttribute(gemm_mma<HIDDEN, false>,
                         cudaFuncAttributeMaxDynamicSharedMemorySize, SMEM_BYTES);

    const int gemm_blocks = (N_NODES + 127) / 128;   // 782

    prep_weights<<<(128 * N_FEATS + 255) / 256, 256>>>(w1, w2);
    gemm_mma<N_FEATS, true><<<gemm_blocks, 256, SMEM_BYTES>>>(
        features, nullptr, nullptr, pW1h, pW1l, pPG, N_NODES);
    aggregate1_kernel<<<(N_NODES * 32 + 255) / 256, 256>>>(neigh);
    gemm_mma<HIDDEN, false><<<gemm_blocks, 256, SMEM_BYTES>>>(
        nullptr, ph1h, ph1l, pW2h, pW2l, pUV, N_NODES);
    final_kernel<<<(NBATCH + 3) / 4, 256>>>(nodes, neigh, wcls, out);
}

// round 5
// speedup vs baseline: 2.2190x; 1.3922x over previous
#include <cuda_runtime.h>
#include <cuda_fp16.h>

#define N_NODES 100000
#define N_FEATS 512
#define HIDDEN  64
#define NSAMP   5
#define NCLS    16
#define NBATCH  16384

typedef unsigned int u32;

// ---------------- scratch (static device globals) ---------------------------
__device__ __half g_W1h[128 * N_FEATS];   // [n=0..127][k] row-major, hi part
__device__ __half g_W1l[128 * N_FEATS];   // lo part
__device__ __half g_W2h[128 * HIDDEN];
__device__ __half g_W2l[128 * HIDDEN];
__device__ __half g_h1[(size_t)N_NODES * HIDDEN];   // layer-1 act (fp16)
__device__ float g_PG[(size_t)N_NODES * 128];       // P | G  (layer-1 pre-act)
__device__ float g_UV[(size_t)N_NODES * 128];       // U | V  (layer-2 pre-act)

// ---------------- helpers ----------------------------------------------------
__device__ __forceinline__ u32 smem_u32(const void* p) {
    u32 a;
    asm("{ .reg .u64 t; cvta.to.shared.u64 t, %1; cvt.u32.u64 %0, t; }"
        : "=r"(a) : "l"(p));
    return a;
}
__device__ __forceinline__ void ldsm4(u32& r0, u32& r1, u32& r2, u32& r3, u32 addr) {
    asm volatile("ldmatrix.sync.aligned.m8n8.x4.shared.b16 {%0,%1,%2,%3}, [%4];"
                 : "=r"(r0), "=r"(r1), "=r"(r2), "=r"(r3) : "r"(addr));
}
__device__ __forceinline__ void mma_f16(float* d, const u32* a, const u32* b) {
    asm volatile(
        "mma.sync.aligned.m16n8k16.row.col.f32.f16.f16.f32 "
        "{%0,%1,%2,%3}, {%4,%5,%6,%7}, {%8,%9}, {%0,%1,%2,%3};"
        : "+f"(d[0]), "+f"(d[1]), "+f"(d[2]), "+f"(d[3])
        : "r"(a[0]), "r"(a[1]), "r"(a[2]), "r"(a[3]), "r"(b[0]), "r"(b[1]));
}
__device__ __forceinline__ void cpasync16(u32 dst, const void* src, int srcsize) {
    asm volatile("cp.async.cg.shared.global [%0], [%1], 16, %2;"
                 :: "r"(dst), "l"(src), "r"(srcsize) : "memory");
}
__device__ __forceinline__ void cpcommit() {
    asm volatile("cp.async.commit_group;" ::: "memory");
}
__device__ __forceinline__ void cpwait0() {
    asm volatile("cp.async.wait_group 0;" ::: "memory");
}
#define SW128(x) ((x) ^ (((x) >> 3) & 0x70))

// smem: 2 buffers x (A 16KB | BH 16KB | BL 16KB). All rows are 128B (SW128).
#define BUF_BYTES 49152
#define OFF_A  0
#define OFF_BH 16384
#define OFF_BL 32768
#define SMEM_BYTES (2 * BUF_BYTES)   // 96 KB

// ---------------------------------------------------------------------------
// Weight prep: split fp32 weights into fp16 hi/lo, [n=0..127][k] row-major
// (n<64 -> self block, n>=64 -> neighbor block).
// ---------------------------------------------------------------------------
__global__ void prep_weights(const float* __restrict__ w1, const float* __restrict__ w2) {
    int idx = blockIdx.x * 256 + threadIdx.x;
    if (idx < 128 * N_FEATS) {
        int n = idx / N_FEATS, k = idx % N_FEATS;
        float v = (n < 64) ? w1[n * (2 * N_FEATS) + k]
                           : w1[(n - 64) * (2 * N_FEATS) + N_FEATS + k];
        __half h = __float2half_rn(v);
        g_W1h[idx] = h;
        g_W1l[idx] = __float2half_rn(v - __half2float(h));
    }
    if (idx < 128 * HIDDEN) {
        int n = idx / HIDDEN, k = idx % HIDDEN;
        float v = (n < 64) ? w2[n * (2 * HIDDEN) + k]
                           : w2[(n - 64) * (2 * HIDDEN) + HIDDEN + k];
        __half h = __float2half_rn(v);
        g_W2h[idx] = h;
        g_W2l[idx] = __float2half_rn(v - __half2float(h));
    }
}

// ---------------------------------------------------------------------------
// Asymmetric-split fp16 HMMA GEMM:  C[M,128] = A[M,K] @ (Bh + Bl)[128,K]^T
// A single fp16 (rounded), B split hi/lo. fp32 accumulate. 128x128 CTA tile,
// 8 warps (warp tile 64x32), KC=64, SW128 smem, cp.async double buffering.
// ---------------------------------------------------------------------------
template <int K, bool AFP32>
__global__ __launch_bounds__(256, 2)
void gemm_mma(const float* __restrict__ Af,
              const __half* __restrict__ Ah,
              const __half* __restrict__ Bh,
              const __half* __restrict__ Bl,
              float* __restrict__ Cm, int M) {
    constexpr int KC = 64;
    constexpr int NCH = K / KC;

    extern __shared__ __align__(1024) char smem[];
    const u32 sb = smem_u32(smem);
    const int tid  = threadIdx.x;
    const int wid  = tid >> 5;
    const int lane = tid & 31;
    const int wm   = (wid & 1) * 64;       // warp M offset
    const int wn   = (wid >> 1) * 32;      // warp N offset
    const int row0 = blockIdx.x * 128;

    // loader coords: thread owns half a 128B row (4 x 16B pieces)
    const int lrow  = tid >> 1;            // 0..127
    const int lhalf = (tid & 1) * 32;      // element offset (fp16)
    const u32 rowoff = (u32)lrow * 128 + (u32)(tid & 1) * 64;
    const bool arow_ok = (row0 + lrow) < M;

    uint4 areg[4];   // staged fp16 A pieces (AFP32 path only)

    auto loadA_regs = [&](int k0) {
        const float* src = Af + (size_t)(row0 + lrow) * K + k0 + lhalf;
#pragma unroll
        for (int j = 0; j < 4; j++) {
            float f[8];
            if (arow_ok) {
                float4 v0 = *(const float4*)(src + j * 8);
                float4 v1 = *(const float4*)(src + j * 8 + 4);
                f[0]=v0.x; f[1]=v0.y; f[2]=v0.z; f[3]=v0.w;
                f[4]=v1.x; f[5]=v1.y; f[6]=v1.z; f[7]=v1.w;
            } else {
#pragma unroll
                for (int e = 0; e < 8; e++) f[e] = 0.f;
            }
            __half2 p0 = __floats2half2_rn(f[0], f[1]);
            __half2 p1 = __floats2half2_rn(f[2], f[3]);
            __half2 p2 = __floats2half2_rn(f[4], f[5]);
            __half2 p3 = __floats2half2_rn(f[6], f[7]);
            areg[j] = make_uint4(*(u32*)&p0, *(u32*)&p1, *(u32*)&p2, *(u32*)&p3);
        }
    };
    auto stsA = [&](int buf) {
        u32 base = sb + buf * BUF_BYTES + OFF_A;
#pragma unroll
        for (int j = 0; j < 4; j++)
            *(uint4*)(smem + (base - sb) + SW128(rowoff + j * 16)) = areg[j];
    };
    auto issueA_async = [&](int k0, int buf) {   // !AFP32: A already fp16
        u32 base = sb + buf * BUF_BYTES + OFF_A;
        const __half* src = Ah + (size_t)(arow_ok ? (row0 + lrow) : 0) * K + k0 + lhalf;
        int sz = arow_ok ? 16 : 0;
#pragma unroll
        for (int j = 0; j < 4; j++)
            cpasync16(base + SW128(rowoff + j * 16), src + j * 8, sz);
    };
    auto issueB_async = [&](int k0, int buf) {
        u32 bh = sb + buf * BUF_BYTES + OFF_BH;
        u32 bl = sb + buf * BUF_BYTES + OFF_BL;
        const __half* sh = Bh + (size_t)lrow * K + k0 + lhalf;
        const __half* sl = Bl + (size_t)lrow * K + k0 + lhalf;
#pragma unroll
        for (int j = 0; j < 4; j++) {
            u32 off = SW128(rowoff + j * 16);
            cpasync16(bh + off, sh + j * 8, 16);
            cpasync16(bl + off, sl + j * 8, 16);
        }
    };

    // ldmatrix lane coords
    const int grp = lane >> 3, lr = lane & 7;
    const int a_m  = wm + (grp & 1) * 8 + lr;
    const int a_kb = (grp >> 1) * 16;
    const int b_n  = wn + (grp >> 1) * 8 + lr;
    const int b_kb = (grp & 1) * 16;

    float acc[4][4][4];
#pragma unroll
    for (int i = 0; i < 4; i++)
#pragma unroll
        for (int j = 0; j < 4; j++)
#pragma unroll
            for (int c = 0; c < 4; c++) acc[i][j][c] = 0.f;

    // prologue: fill buffer 0
    if constexpr (AFP32) { loadA_regs(0); stsA(0); }
    else                 { issueA_async(0, 0); }
    issueB_async(0, 0);
    cpcommit();
    cpwait0();
    __syncthreads();

    for (int t = 0; t < NCH; ++t) {
        int buf = t & 1;
        if (t + 1 < NCH) {
            if constexpr (AFP32) loadA_regs((t + 1) * KC);
            else                 issueA_async((t + 1) * KC, buf ^ 1);
            issueB_async((t + 1) * KC, buf ^ 1);
            cpcommit();
        }

        u32 sA  = sb + buf * BUF_BYTES + OFF_A;
        u32 sBH = sb + buf * BUF_BYTES + OFF_BH;
        u32 sBL = sb + buf * BUF_BYTES + OFF_BL;

#pragma unroll
        for (int ks = 0; ks < 4; ks++) {
            u32 a4[4][4];
#pragma unroll
            for (int mt = 0; mt < 4; mt++) {
                u32 off = SW128((u32)((a_m + mt * 16) * 128 + ks * 32 + a_kb));
                ldsm4(a4[mt][0], a4[mt][1], a4[mt][2], a4[mt][3], sA + off);
            }
            u32 bh4[4][2], bl4[4][2];
#pragma unroll
            for (int p = 0; p < 2; p++) {
                u32 off = SW128((u32)((b_n + p * 16) * 128 + ks * 32 + b_kb));
                u32 r0, r1, r2, r3;
                ldsm4(r0, r1, r2, r3, sBH + off);
                bh4[2 * p][0] = r0; bh4[2 * p][1] = r1;
                bh4[2 * p + 1][0] = r2; bh4[2 * p + 1][1] = r3;
                ldsm4(r0, r1, r2, r3, sBL + off);
                bl4[2 * p][0] = r0; bl4[2 * p][1] = r1;
                bl4[2 * p + 1][0] = r2; bl4[2 * p + 1][1] = r3;
            }
#pragma unroll
            for (int mt = 0; mt < 4; mt++)
#pragma unroll
                for (int nt = 0; nt < 4; nt++) {
                    mma_f16(acc[mt][nt], a4[mt], bh4[nt]);
                    mma_f16(acc[mt][nt], a4[mt], bl4[nt]);
                }
        }

        if (t + 1 < NCH) {
            if constexpr (AFP32) stsA(buf ^ 1);   // buf^1 safe: freed at prior sync
            cpwait0();
            __syncthreads();
        }
    }

    // epilogue: fragment -> global fp32
    const int tm = lane >> 2;
    const int tn = (lane & 3) * 2;
#pragma unroll
    for (int mt = 0; mt < 4; mt++) {
        int gm0 = row0 + wm + mt * 16 + tm;
#pragma unroll
        for (int nt = 0; nt < 4; nt++) {
            int gn = wn + nt * 8 + tn;
            if (gm0 < M)
                *(float2*)(Cm + (size_t)gm0 * 128 + gn) =
                    make_float2(acc[mt][nt][0], acc[mt][nt][1]);
            if (gm0 + 8 < M)
                *(float2*)(Cm + (size_t)(gm0 + 8) * 128 + gn) =
                    make_float2(acc[mt][nt][2], acc[mt][nt][3]);
        }
    }
}

// ---------------------------------------------------------------------------
// Layer-1 aggregation in 64-dim space, emitting h1 as fp16:
//   h1[n] = relu(P[n] + 0.2 * sum_s G[neigh[n,s]])
// ---------------------------------------------------------------------------
__global__ void aggregate1_kernel(const int* __restrict__ neigh) {
    int gw   = (blockIdx.x * 256 + threadIdx.x) >> 5;
    int lane = threadIdx.x & 31;
    if (gw >= N_NODES) return;

    const float* base = g_PG + (size_t)gw * 128;
    float2 s = *(const float2*)(base + lane * 2);
    float ax = 0.f, ay = 0.f;
#pragma unroll
    for (int j = 0; j < NSAMP; j++) {
        int nb = __ldg(&neigh[gw * NSAMP + j]);
        float2 v = *(const float2*)(g_PG + (size_t)nb * 128 + 64 + lane * 2);
        ax += v.x; ay += v.y;
    }
    float hx = fmaxf(fmaf(ax, 0.2f, s.x), 0.f);
    float hy = fmaxf(fmaf(ay, 0.2f, s.y), 0.f);
    *(__half2*)(g_h1 + (size_t)gw * 64 + lane * 2) = __floats2half2_rn(hx, hy);
}

// ---------------------------------------------------------------------------
// Final: h2 = relu(U[n] + 0.2 * sum_s V[neigh[n,s]]); out = h2 @ w_cls.T
// ---------------------------------------------------------------------------
__global__ __launch_bounds__(256)
void final_kernel(const int* __restrict__ nodes, const int* __restrict__ neigh,
                  const float* __restrict__ wcls, float* __restrict__ out) {
    __shared__ float h2s[4][64];
    __shared__ float wcs[16][66];

    int tid = threadIdx.x;
    for (int i = tid; i < NCLS * HIDDEN; i += 256)
        wcs[i >> 6][i & 63] = wcls[i];

    int sub = tid >> 6;
    int h   = tid & 63;
    int b   = blockIdx.x * 4 + sub;

    float val = 0.f;
    if (b < NBATCH) {
        int n = nodes[b];
        float self = g_UV[(size_t)n * 128 + h];
        float acc = 0.f;
#pragma unroll
        for (int j = 0; j < NSAMP; j++) {
            int nb = __ldg(&neigh[n * NSAMP + j]);
            acc += g_UV[(size_t)nb * 128 + 64 + h];
        }
        val = fmaxf(fmaf(acc, 0.2f, self), 0.f);
    }
    h2s[sub][h] = val;
    __syncthreads();

    if (tid < 64) {
        int sub2 = tid >> 4;
        int c    = tid & 15;
        int b2   = blockIdx.x * 4 + sub2;
        if (b2 < NBATCH) {
            float acc = 0.f;
#pragma unroll
            for (int k = 0; k < HIDDEN; k++)
                acc = fmaf(wcs[c][k], h2s[sub2][k], acc);
            out[b2 * NCLS + c] = acc;
        }
    }
}

// ---------------------------------------------------------------------------
extern "C" void kernel_launch(void* const* d_in, const int* in_sizes, int n_in,
                              void* d_out, int out_size) {
    const float* features = (const float*)d_in[0];
    const float* w1       = (const float*)d_in[1];
    const float* w2       = (const float*)d_in[2];
    const float* wcls     = (const float*)d_in[3];
    const int*   nodes    = (const int*)d_in[4];
    const int*   neigh    = (const int*)d_in[5];
    float*       out      = (float*)d_out;

    __half *pW1h, *pW1l, *pW2h, *pW2l, *ph1;
    float *pPG, *pUV;
    cudaGetSymbolAddress((void**)&pW1h, g_W1h);
    cudaGetSymbolAddress((void**)&pW1l, g_W1l);
    cudaGetSymbolAddress((void**)&pW2h, g_W2h);
    cudaGetSymbolAddress((void**)&pW2l, g_W2l);
    cudaGetSymbolAddress((void**)&ph1,  g_h1);
    cudaGetSymbolAddress((void**)&pPG,  g_PG);
    cudaGetSymbolAddress((void**)&pUV,  g_UV);

    cudaFuncSetAttribute(gemm_mma<N_FEATS, true>,
                         cudaFuncAttributeMaxDynamicSharedMemorySize, SMEM_BYTES);
    cudaFuncSetAttribute(gemm_mma<HIDDEN, false>,
                         cudaFuncAttributeMaxDynamicSharedMemorySize, SMEM_BYTES);

    const int gemm_blocks = (N_NODES + 127) / 128;   // 782

    prep_weights<<<(128 * N_FEATS + 255) / 256, 256>>>(w1, w2);
    gemm_mma<N_FEATS, true><<<gemm_blocks, 256, SMEM_BYTES>>>(
        features, nullptr, pW1h, pW1l, pPG, N_NODES);
    aggregate1_kernel<<<(N_NODES * 32 + 255) / 256, 256>>>(neigh);
    gemm_mma<HIDDEN, false><<<gemm_blocks, 256, SMEM_BYTES>>>(
        nullptr, ph1, pW2h, pW2l, pUV, N_NODES);
    final_kernel<<<(NBATCH + 3) / 4, 256>>>(nodes, neigh, wcls, out);
}

// round 6
// speedup vs baseline: 2.8965x; 1.3053x over previous
#include <cuda_runtime.h>
#include <cuda_fp16.h>

#define N_NODES 100000
#define N_FEATS 512
#define HIDDEN  64
#define NSAMP   5
#define NCLS    16
#define NBATCH  16384

typedef unsigned int u32;

// ---------------- scratch (static device globals) ---------------------------
__device__ __half g_W1[128 * N_FEATS];   // [n=0..127][k] row-major fp16
__device__ __half g_W2[128 * HIDDEN];
__device__ __half g_h1[(size_t)N_NODES * HIDDEN];   // layer-1 act (fp16)
__device__ float  g_PG[(size_t)N_NODES * 128];      // P | G  (fp32)
__device__ __half g_UV[(size_t)N_NODES * 128];      // U | V  (fp16)

// ---------------- helpers ----------------------------------------------------
__device__ __forceinline__ u32 smem_u32(const void* p) {
    u32 a;
    asm("{ .reg .u64 t; cvta.to.shared.u64 t, %1; cvt.u32.u64 %0, t; }"
        : "=r"(a) : "l"(p));
    return a;
}
__device__ __forceinline__ void ldsm4(u32& r0, u32& r1, u32& r2, u32& r3, u32 addr) {
    asm volatile("ldmatrix.sync.aligned.m8n8.x4.shared.b16 {%0,%1,%2,%3}, [%4];"
                 : "=r"(r0), "=r"(r1), "=r"(r2), "=r"(r3) : "r"(addr));
}
__device__ __forceinline__ void mma_f16(float* d, const u32* a, const u32* b) {
    asm volatile(
        "mma.sync.aligned.m16n8k16.row.col.f32.f16.f16.f32 "
        "{%0,%1,%2,%3}, {%4,%5,%6,%7}, {%8,%9}, {%0,%1,%2,%3};"
        : "+f"(d[0]), "+f"(d[1]), "+f"(d[2]), "+f"(d[3])
        : "r"(a[0]), "r"(a[1]), "r"(a[2]), "r"(a[3]), "r"(b[0]), "r"(b[1]));
}
__device__ __forceinline__ void cpasync16(u32 dst, const void* src, int srcsize) {
    asm volatile("cp.async.cg.shared.global [%0], [%1], 16, %2;"
                 :: "r"(dst), "l"(src), "r"(srcsize) : "memory");
}
__device__ __forceinline__ void cpcommit() {
    asm volatile("cp.async.commit_group;" ::: "memory");
}
__device__ __forceinline__ void cpwait0() {
    asm volatile("cp.async.wait_group 0;" ::: "memory");
}
#define SW128(x) ((x) ^ (((x) >> 3) & 0x70))

// smem: 2 buffers x (A 16KB | B 16KB). All rows are 128B (SW128).
#define BUF_BYTES 32768
#define OFF_A  0
#define OFF_B  16384
#define SMEM_BYTES (2 * BUF_BYTES)   // 64 KB

// ---------------------------------------------------------------------------
// Weight prep: round fp32 weights to fp16, [n=0..127][k] row-major
// (n<64 -> self block, n>=64 -> neighbor block).
// ---------------------------------------------------------------------------
__global__ void prep_weights(const float* __restrict__ w1, const float* __restrict__ w2) {
    int idx = blockIdx.x * 256 + threadIdx.x;
    if (idx < 128 * N_FEATS) {
        int n = idx / N_FEATS, k = idx % N_FEATS;
        float v = (n < 64) ? w1[n * (2 * N_FEATS) + k]
                           : w1[(n - 64) * (2 * N_FEATS) + N_FEATS + k];
        g_W1[idx] = __float2half_rn(v);
    }
    if (idx < 128 * HIDDEN) {
        int n = idx / HIDDEN, k = idx % HIDDEN;
        float v = (n < 64) ? w2[n * (2 * HIDDEN) + k]
                           : w2[(n - 64) * (2 * HIDDEN) + HIDDEN + k];
        g_W2[idx] = __float2half_rn(v);
    }
}

// ---------------------------------------------------------------------------
// fp16 HMMA GEMM:  C[M,128] = A[M,K] @ B[128,K]^T, fp32 accumulate.
// 128x128 CTA tile, 8 warps (warp tile 64x32), KC=64, SW128 smem,
// cp.async double buffering. AFP32: A converted fp32->fp16 in-flight.
// CHALF: C written as fp16 instead of fp32.
// ---------------------------------------------------------------------------
template <int K, bool AFP32, bool CHALF>
__global__ __launch_bounds__(256, 2)
void gemm_mma(const float* __restrict__ Af,
              const __half* __restrict__ Ah,
              const __half* __restrict__ Bm,
              void* __restrict__ Cm, int M) {
    constexpr int KC = 64;
    constexpr int NCH = K / KC;

    extern __shared__ __align__(1024) char smem[];
    const u32 sb = smem_u32(smem);
    const int tid  = threadIdx.x;
    const int wid  = tid >> 5;
    const int lane = tid & 31;
    const int wm   = (wid & 1) * 64;       // warp M offset
    const int wn   = (wid >> 1) * 32;      // warp N offset
    const int row0 = blockIdx.x * 128;

    // loader coords: thread owns half a 128B row (4 x 16B pieces)
    const int lrow  = tid >> 1;            // 0..127
    const int lhalf = (tid & 1) * 32;      // element offset (fp16)
    const u32 rowoff = (u32)lrow * 128 + (u32)(tid & 1) * 64;
    const bool arow_ok = (row0 + lrow) < M;

    uint4 areg[4];   // staged fp16 A pieces (AFP32 path only)

    auto loadA_regs = [&](int k0) {
        const float* src = Af + (size_t)(row0 + lrow) * K + k0 + lhalf;
#pragma unroll
        for (int j = 0; j < 4; j++) {
            float f[8];
            if (arow_ok) {
                float4 v0 = *(const float4*)(src + j * 8);
                float4 v1 = *(const float4*)(src + j * 8 + 4);
                f[0]=v0.x; f[1]=v0.y; f[2]=v0.z; f[3]=v0.w;
                f[4]=v1.x; f[5]=v1.y; f[6]=v1.z; f[7]=v1.w;
            } else {
#pragma unroll
                for (int e = 0; e < 8; e++) f[e] = 0.f;
            }
            __half2 p0 = __floats2half2_rn(f[0], f[1]);
            __half2 p1 = __floats2half2_rn(f[2], f[3]);
            __half2 p2 = __floats2half2_rn(f[4], f[5]);
            __half2 p3 = __floats2half2_rn(f[6], f[7]);
            areg[j] = make_uint4(*(u32*)&p0, *(u32*)&p1, *(u32*)&p2, *(u32*)&p3);
        }
    };
    auto stsA = [&](int buf) {
        char* base = smem + buf * BUF_BYTES + OFF_A;
#pragma unroll
        for (int j = 0; j < 4; j++)
            *(uint4*)(base + SW128(rowoff + j * 16)) = areg[j];
    };
    auto issueA_async = [&](int k0, int buf) {   // !AFP32: A already fp16
        u32 base = sb + buf * BUF_BYTES + OFF_A;
        const __half* src = Ah + (size_t)(arow_ok ? (row0 + lrow) : 0) * K + k0 + lhalf;
        int sz = arow_ok ? 16 : 0;
#pragma unroll
        for (int j = 0; j < 4; j++)
            cpasync16(base + SW128(rowoff + j * 16), src + j * 8, sz);
    };
    auto issueB_async = [&](int k0, int buf) {
        u32 bbase = sb + buf * BUF_BYTES + OFF_B;
        const __half* sh = Bm + (size_t)lrow * K + k0 + lhalf;
#pragma unroll
        for (int j = 0; j < 4; j++)
            cpasync16(bbase + SW128(rowoff + j * 16), sh + j * 8, 16);
    };

    // ldmatrix lane coords
    const int grp = lane >> 3, lr = lane & 7;
    const int a_m  = wm + (grp & 1) * 8 + lr;
    const int a_kb = (grp >> 1) * 16;
    const int b_n  = wn + (grp >> 1) * 8 + lr;
    const int b_kb = (grp & 1) * 16;

    float acc[4][4][4];
#pragma unroll
    for (int i = 0; i < 4; i++)
#pragma unroll
        for (int j = 0; j < 4; j++)
#pragma unroll
            for (int c = 0; c < 4; c++) acc[i][j][c] = 0.f;

    // prologue: fill buffer 0
    if constexpr (AFP32) { loadA_regs(0); stsA(0); }
    else                 { issueA_async(0, 0); }
    issueB_async(0, 0);
    cpcommit();
    cpwait0();
    __syncthreads();

    for (int t = 0; t < NCH; ++t) {
        int buf = t & 1;
        if (t + 1 < NCH) {
            if constexpr (AFP32) loadA_regs((t + 1) * KC);
            else                 issueA_async((t + 1) * KC, buf ^ 1);
            issueB_async((t + 1) * KC, buf ^ 1);
            cpcommit();
        }

        u32 sA = sb + buf * BUF_BYTES + OFF_A;
        u32 sB = sb + buf * BUF_BYTES + OFF_B;

#pragma unroll
        for (int ks = 0; ks < 4; ks++) {
            u32 a4[4][4];
#pragma unroll
            for (int mt = 0; mt < 4; mt++) {
                u32 off = SW128((u32)((a_m + mt * 16) * 128 + ks * 32 + a_kb));
                ldsm4(a4[mt][0], a4[mt][1], a4[mt][2], a4[mt][3], sA + off);
            }
            u32 b4[4][2];
#pragma unroll
            for (int p = 0; p < 2; p++) {
                u32 off = SW128((u32)((b_n + p * 16) * 128 + ks * 32 + b_kb));
                u32 r0, r1, r2, r3;
                ldsm4(r0, r1, r2, r3, sB + off);
                b4[2 * p][0] = r0; b4[2 * p][1] = r1;
                b4[2 * p + 1][0] = r2; b4[2 * p + 1][1] = r3;
            }
#pragma unroll
            for (int mt = 0; mt < 4; mt++)
#pragma unroll
                for (int nt = 0; nt < 4; nt++)
                    mma_f16(acc[mt][nt], a4[mt], b4[nt]);
        }

        if (t + 1 < NCH) {
            if constexpr (AFP32) stsA(buf ^ 1);   // buf^1 freed at prior sync
            cpwait0();
            __syncthreads();
        }
    }

    // epilogue: fragment -> global (fp32 or fp16)
    const int tm = lane >> 2;
    const int tn = (lane & 3) * 2;
#pragma unroll
    for (int mt = 0; mt < 4; mt++) {
        int gm0 = row0 + wm + mt * 16 + tm;
#pragma unroll
        for (int nt = 0; nt < 4; nt++) {
            int gn = wn + nt * 8 + tn;
            if constexpr (CHALF) {
                __half* Ch = (__half*)Cm;
                __half2 v01 = __floats2half2_rn(acc[mt][nt][0], acc[mt][nt][1]);
                __half2 v23 = __floats2half2_rn(acc[mt][nt][2], acc[mt][nt][3]);
                if (gm0 < M)     *(__half2*)(Ch + (size_t)gm0 * 128 + gn) = v01;
                if (gm0 + 8 < M) *(__half2*)(Ch + (size_t)(gm0 + 8) * 128 + gn) = v23;
            } else {
                float* Cf = (float*)Cm;
                if (gm0 < M)
                    *(float2*)(Cf + (size_t)gm0 * 128 + gn) =
                        make_float2(acc[mt][nt][0], acc[mt][nt][1]);
                if (gm0 + 8 < M)
                    *(float2*)(Cf + (size_t)(gm0 + 8) * 128 + gn) =
                        make_float2(acc[mt][nt][2], acc[mt][nt][3]);
            }
        }
    }
}

// ---------------------------------------------------------------------------
// Layer-1 aggregation in 64-dim space, emitting h1 as fp16:
//   h1[n] = relu(P[n] + 0.2 * sum_s G[neigh[n,s]])
// ---------------------------------------------------------------------------
__global__ void aggregate1_kernel(const int* __restrict__ neigh) {
    int gw   = (blockIdx.x * 256 + threadIdx.x) >> 5;
    int lane = threadIdx.x & 31;
    if (gw >= N_NODES) return;

    const float* base = g_PG + (size_t)gw * 128;
    float2 s = *(const float2*)(base + lane * 2);
    float ax = 0.f, ay = 0.f;
#pragma unroll
    for (int j = 0; j < NSAMP; j++) {
        int nb = __ldg(&neigh[gw * NSAMP + j]);
        float2 v = *(const float2*)(g_PG + (size_t)nb * 128 + 64 + lane * 2);
        ax += v.x; ay += v.y;
    }
    float hx = fmaxf(fmaf(ax, 0.2f, s.x), 0.f);
    float hy = fmaxf(fmaf(ay, 0.2f, s.y), 0.f);
    *(__half2*)(g_h1 + (size_t)gw * 64 + lane * 2) = __floats2half2_rn(hx, hy);
}

// ---------------------------------------------------------------------------
// Final: h2 = relu(U[n] + 0.2 * sum_s V[neigh[n,s]]); out = h2 @ w_cls.T
// UV is fp16 now.
// ---------------------------------------------------------------------------
__global__ __launch_bounds__(256)
void final_kernel(const int* __restrict__ nodes, const int* __restrict__ neigh,
                  const float* __restrict__ wcls, float* __restrict__ out) {
    __shared__ float h2s[4][64];
    __shared__ float wcs[16][66];

    int tid = threadIdx.x;
    for (int i = tid; i < NCLS * HIDDEN; i += 256)
        wcs[i >> 6][i & 63] = wcls[i];

    int sub = tid >> 6;
    int h   = tid & 63;
    int b   = blockIdx.x * 4 + sub;

    float val = 0.f;
    if (b < NBATCH) {
        int n = nodes[b];
        float self = __half2float(g_UV[(size_t)n * 128 + h]);
        float acc = 0.f;
#pragma unroll
        for (int j = 0; j < NSAMP; j++) {
            int nb = __ldg(&neigh[n * NSAMP + j]);
            acc += __half2float(g_UV[(size_t)nb * 128 + 64 + h]);
        }
        val = fmaxf(fmaf(acc, 0.2f, self), 0.f);
    }
    h2s[sub][h] = val;
    __syncthreads();

    if (tid < 64) {
        int sub2 = tid >> 4;
        int c    = tid & 15;
        int b2   = blockIdx.x * 4 + sub2;
        if (b2 < NBATCH) {
            float acc = 0.f;
#pragma unroll
            for (int k = 0; k < HIDDEN; k++)
                acc = fmaf(wcs[c][k], h2s[sub2][k], acc);
            out[b2 * NCLS + c] = acc;
        }
    }
}

// ---------------------------------------------------------------------------
extern "C" void kernel_launch(void* const* d_in, const int* in_sizes, int n_in,
                              void* d_out, int out_size) {
    const float* features = (const float*)d_in[0];
    const float* w1       = (const float*)d_in[1];
    const float* w2       = (const float*)d_in[2];
    const float* wcls     = (const float*)d_in[3];
    const int*   nodes    = (const int*)d_in[4];
    const int*   neigh    = (const int*)d_in[5];
    float*       out      = (float*)d_out;

    __half *pW1, *pW2, *ph1, *pUV;
    float *pPG;
    cudaGetSymbolAddress((void**)&pW1, g_W1);
    cudaGetSymbolAddress((void**)&pW2, g_W2);
    cudaGetSymbolAddress((void**)&ph1, g_h1);
    cudaGetSymbolAddress((void**)&pPG, g_PG);
    cudaGetSymbolAddress((void**)&pUV, g_UV);

    cudaFuncSetAttribute(gemm_mma<N_FEATS, true, false>,
                         cudaFuncAttributeMaxDynamicSharedMemorySize, SMEM_BYTES);
    cudaFuncSetAttribute(gemm_mma<HIDDEN, false, true>,
                         cudaFuncAttributeMaxDynamicSharedMemorySize, SMEM_BYTES);

    const int gemm_blocks = (N_NODES + 127) / 128;   // 782

    prep_weights<<<(128 * N_FEATS + 255) / 256, 256>>>(w1, w2);
    gemm_mma<N_FEATS, true, false><<<gemm_blocks, 256, SMEM_BYTES>>>(
        features, nullptr, pW1, pPG, N_NODES);
    aggregate1_kernel<<<(N_NODES * 32 + 255) / 256, 256>>>(neigh);
    gemm_mma<HIDDEN, false, true><<<gemm_blocks, 256, SMEM_BYTES>>>(
        nullptr, ph1, pW2, pUV, N_NODES);
    final_kernel<<<(NBATCH + 3) / 4, 256>>>(nodes, neigh, wcls, out);
}

// round 7
// speedup vs baseline: 3.2285x; 1.1146x over previous
#include <cuda_runtime.h>
#include <cuda_fp16.h>

#define N_NODES 100000
#define N_FEATS 512
#define HIDDEN  64
#define NSAMP   5
#define NCLS    16
#define NBATCH  16384

typedef unsigned int u32;

// ---------------- scratch (static device globals) ---------------------------
__device__ __half g_W1[128 * N_FEATS];   // [n=0..127][k] row-major fp16
__device__ __half g_W2[128 * HIDDEN];
__device__ __half g_h1[(size_t)N_NODES * HIDDEN];   // layer-1 act (fp16)
__device__ __half g_PG[(size_t)N_NODES * 128];      // P | G  (fp16)
__device__ __half g_UV[(size_t)N_NODES * 128];      // U | V  (fp16)

// ---------------- helpers ----------------------------------------------------
__device__ __forceinline__ u32 smem_u32(const void* p) {
    u32 a;
    asm("{ .reg .u64 t; cvta.to.shared.u64 t, %1; cvt.u32.u64 %0, t; }"
        : "=r"(a) : "l"(p));
    return a;
}
__device__ __forceinline__ void ldsm4(u32& r0, u32& r1, u32& r2, u32& r3, u32 addr) {
    asm volatile("ldmatrix.sync.aligned.m8n8.x4.shared.b16 {%0,%1,%2,%3}, [%4];"
                 : "=r"(r0), "=r"(r1), "=r"(r2), "=r"(r3) : "r"(addr));
}
__device__ __forceinline__ void mma_f16(float* d, const u32* a, const u32* b) {
    asm volatile(
        "mma.sync.aligned.m16n8k16.row.col.f32.f16.f16.f32 "
        "{%0,%1,%2,%3}, {%4,%5,%6,%7}, {%8,%9}, {%0,%1,%2,%3};"
        : "+f"(d[0]), "+f"(d[1]), "+f"(d[2]), "+f"(d[3])
        : "r"(a[0]), "r"(a[1]), "r"(a[2]), "r"(a[3]), "r"(b[0]), "r"(b[1]));
}
__device__ __forceinline__ void cpasync16(u32 dst, const void* src, int srcsize) {
    asm volatile("cp.async.cg.shared.global [%0], [%1], 16, %2;"
                 :: "r"(dst), "l"(src), "r"(srcsize) : "memory");
}
__device__ __forceinline__ void cpcommit() {
    asm volatile("cp.async.commit_group;" ::: "memory");
}
__device__ __forceinline__ void cpwait0() {
    asm volatile("cp.async.wait_group 0;" ::: "memory");
}
__device__ __forceinline__ void cpwait1() {
    asm volatile("cp.async.wait_group 1;" ::: "memory");
}
#define SW128(x) ((x) ^ (((x) >> 3) & 0x70))
#define SW64(x)  ((x) ^ (((x) >> 3) & 0x30))

// ---------------------------------------------------------------------------
// Weight prep: round fp32 weights to fp16, [n=0..127][k] row-major
// (n<64 -> self block, n>=64 -> neighbor block).
// ---------------------------------------------------------------------------
__global__ void prep_weights(const float* __restrict__ w1, const float* __restrict__ w2) {
    int idx = blockIdx.x * 256 + threadIdx.x;
    if (idx < 128 * N_FEATS) {
        int n = idx / N_FEATS, k = idx % N_FEATS;
        float v = (n < 64) ? w1[n * (2 * N_FEATS) + k]
                           : w1[(n - 64) * (2 * N_FEATS) + N_FEATS + k];
        g_W1[idx] = __float2half_rn(v);
    }
    if (idx < 128 * HIDDEN) {
        int n = idx / HIDDEN, k = idx % HIDDEN;
        float v = (n < 64) ? w2[n * (2 * HIDDEN) + k]
                           : w2[(n - 64) * (2 * HIDDEN) + HIDDEN + k];
        g_W2[idx] = __float2half_rn(v);
    }
}

// ===========================================================================
// GEMM1: C[M,128] (fp16) = A[M,512] (fp32, converted in smem) @ W1[128,512]^T
// 128x128 CTA tile, 8 warps (64x32 warp tiles), KC=32, 3-stage cp.async
// (A staged as fp32, converted smem->smem to fp16), fp32 accumulate.
// ===========================================================================
#define KC1   32
#define NCH1  (N_FEATS / KC1)          // 16
#define SG_A  0                         // A fp32 stage: 128 rows x 128B (SW128)
#define SG_B  16384                     // B fp16 stage: 128 rows x 64B (SW64)
#define STG_BYTES 24576
#define WRK_OFF   73728                 // 3 stages
#define WRK_BYTES 8192                  // A fp16 work: 128 rows x 64B (SW64)
#define G1_SMEM   (WRK_OFF + 2 * WRK_BYTES)   // 90112

__global__ __launch_bounds__(256, 2)
void gemm1_tc(const float* __restrict__ Af, const __half* __restrict__ Bm,
              __half* __restrict__ Cm, int M) {
    extern __shared__ __align__(1024) char smem[];
    const u32 sb = smem_u32(smem);
    const int tid  = threadIdx.x;
    const int wid  = tid >> 5;
    const int lane = tid & 31;
    const int wm   = (wid & 1) * 64;
    const int wn   = (wid >> 1) * 32;
    const int row0 = blockIdx.x * 128;

    const int lrow  = tid >> 1;        // 0..127
    const int lhalf = tid & 1;
    const bool arow_ok = (row0 + lrow) < M;
    const u32 aoff = (u32)lrow * 128 + (u32)lhalf * 64;   // A stage byte offset
    const u32 woff = (u32)lrow * 64 + (u32)lhalf * 32;    // fp16 row byte offset

    auto issue_stage = [&](int c) {
        int slot = c % 3;
        u32 abase = sb + slot * STG_BYTES + SG_A;
        u32 bbase = sb + slot * STG_BYTES + SG_B;
        int k0 = c * KC1;
        const float* asrc = Af + (size_t)(arow_ok ? row0 + lrow : 0) * N_FEATS
                               + k0 + lhalf * 16;
        int sz = arow_ok ? 16 : 0;
#pragma unroll
        for (int j = 0; j < 4; j++)
            cpasync16(abase + SW128(aoff + j * 16), asrc + j * 4, sz);
        const __half* bsrc = Bm + (size_t)lrow * N_FEATS + k0 + lhalf * 16;
#pragma unroll
        for (int j = 0; j < 2; j++)
            cpasync16(bbase + SW64(woff + j * 16), bsrc + j * 8, 16);
        cpcommit();
    };

    auto convert = [&](int t) {
        char* astage = smem + (t % 3) * STG_BYTES + SG_A;
        char* wbase  = smem + WRK_OFF + (t & 1) * WRK_BYTES;
#pragma unroll
        for (int j = 0; j < 2; j++) {
            float4 v0 = *(const float4*)(astage + SW128(aoff + j * 32));
            float4 v1 = *(const float4*)(astage + SW128(aoff + j * 32 + 16));
            __half2 p0 = __floats2half2_rn(v0.x, v0.y);
            __half2 p1 = __floats2half2_rn(v0.z, v0.w);
            __half2 p2 = __floats2half2_rn(v1.x, v1.y);
            __half2 p3 = __floats2half2_rn(v1.z, v1.w);
            *(uint4*)(wbase + SW64(woff + j * 16)) =
                make_uint4(*(u32*)&p0, *(u32*)&p1, *(u32*)&p2, *(u32*)&p3);
        }
    };

    // ldmatrix lane coords
    const int grp = lane >> 3, lr = lane & 7;
    const int a_m  = wm + (grp & 1) * 8 + lr;
    const int a_kb = (grp >> 1) * 16;
    const int b_n  = wn + (grp >> 1) * 8 + lr;
    const int b_kb = (grp & 1) * 16;

    float acc[4][4][4];
#pragma unroll
    for (int i = 0; i < 4; i++)
#pragma unroll
        for (int j = 0; j < 4; j++)
#pragma unroll
            for (int c = 0; c < 4; c++) acc[i][j][c] = 0.f;

    issue_stage(0);
    issue_stage(1);
    issue_stage(2);

    for (int t = 0; t < NCH1; ++t) {
        if (t + 1 < NCH1) cpwait1();   // chunk t arrived (newest may be in flight)
        else              cpwait0();   // last chunk is the newest group
        __syncthreads();               // smem writes visible; prior compute done
        if (t >= 1 && t + 2 < NCH1) issue_stage(t + 2);   // refill freed slot
        convert(t);
        __syncthreads();

        u32 sW = sb + WRK_OFF + (t & 1) * WRK_BYTES;
        u32 sB = sb + (t % 3) * STG_BYTES + SG_B;

#pragma unroll
        for (int ks = 0; ks < 2; ks++) {
            u32 a4[4][4];
#pragma unroll
            for (int mt = 0; mt < 4; mt++) {
                u32 off = SW64((u32)((a_m + mt * 16) * 64 + ks * 32 + a_kb));
                ldsm4(a4[mt][0], a4[mt][1], a4[mt][2], a4[mt][3], sW + off);
            }
            u32 b4[4][2];
#pragma unroll
            for (int p = 0; p < 2; p++) {
                u32 off = SW64((u32)((b_n + p * 16) * 64 + ks * 32 + b_kb));
                u32 r0, r1, r2, r3;
                ldsm4(r0, r1, r2, r3, sB + off);
                b4[2 * p][0] = r0; b4[2 * p][1] = r1;
                b4[2 * p + 1][0] = r2; b4[2 * p + 1][1] = r3;
            }
#pragma unroll
            for (int mt = 0; mt < 4; mt++)
#pragma unroll
                for (int nt = 0; nt < 4; nt++)
                    mma_f16(acc[mt][nt], a4[mt], b4[nt]);
        }
    }

    // epilogue: fp16 output
    const int tm = lane >> 2;
    const int tn = (lane & 3) * 2;
#pragma unroll
    for (int mt = 0; mt < 4; mt++) {
        int gm0 = row0 + wm + mt * 16 + tm;
#pragma unroll
        for (int nt = 0; nt < 4; nt++) {
            int gn = wn + nt * 8 + tn;
            __half2 v01 = __floats2half2_rn(acc[mt][nt][0], acc[mt][nt][1]);
            __half2 v23 = __floats2half2_rn(acc[mt][nt][2], acc[mt][nt][3]);
            if (gm0 < M)     *(__half2*)(Cm + (size_t)gm0 * 128 + gn) = v01;
            if (gm0 + 8 < M) *(__half2*)(Cm + (size_t)(gm0 + 8) * 128 + gn) = v23;
        }
    }
}

// ===========================================================================
// GEMM2: C[M,128] (fp16) = A[M,64] (fp16) @ W2[128,64]^T. Single K chunk.
// ===========================================================================
#define G2_BUF  32768
#define G2_OFFA 0
#define G2_OFFB 16384

__global__ __launch_bounds__(256, 2)
void gemm2_tc(const __half* __restrict__ Ah, const __half* __restrict__ Bm,
              __half* __restrict__ Cm, int M) {
    extern __shared__ __align__(1024) char smem[];
    const u32 sb = smem_u32(smem);
    const int tid  = threadIdx.x;
    const int wid  = tid >> 5;
    const int lane = tid & 31;
    const int wm   = (wid & 1) * 64;
    const int wn   = (wid >> 1) * 32;
    const int row0 = blockIdx.x * 128;

    const int lrow  = tid >> 1;
    const u32 rowoff = (u32)lrow * 128 + (u32)(tid & 1) * 64;
    const bool arow_ok = (row0 + lrow) < M;

    {
        u32 abase = sb + G2_OFFA, bbase = sb + G2_OFFB;
        const __half* asrc = Ah + (size_t)(arow_ok ? row0 + lrow : 0) * HIDDEN
                                + (tid & 1) * 32;
        int sz = arow_ok ? 16 : 0;
        const __half* bsrc = Bm + (size_t)lrow * HIDDEN + (tid & 1) * 32;
#pragma unroll
        for (int j = 0; j < 4; j++) {
            u32 off = SW128(rowoff + j * 16);
            cpasync16(abase + off, asrc + j * 8, sz);
            cpasync16(bbase + off, bsrc + j * 8, 16);
        }
        cpcommit();
        cpwait0();
        __syncthreads();
    }

    const int grp = lane >> 3, lr = lane & 7;
    const int a_m  = wm + (grp & 1) * 8 + lr;
    const int a_kb = (grp >> 1) * 16;
    const int b_n  = wn + (grp >> 1) * 8 + lr;
    const int b_kb = (grp & 1) * 16;

    float acc[4][4][4];
#pragma unroll
    for (int i = 0; i < 4; i++)
#pragma unroll
        for (int j = 0; j < 4; j++)
#pragma unroll
            for (int c = 0; c < 4; c++) acc[i][j][c] = 0.f;

    u32 sA = sb + G2_OFFA, sB = sb + G2_OFFB;
#pragma unroll
    for (int ks = 0; ks < 4; ks++) {
        u32 a4[4][4];
#pragma unroll
        for (int mt = 0; mt < 4; mt++) {
            u32 off = SW128((u32)((a_m + mt * 16) * 128 + ks * 32 + a_kb));
            ldsm4(a4[mt][0], a4[mt][1], a4[mt][2], a4[mt][3], sA + off);
        }
        u32 b4[4][2];
#pragma unroll
        for (int p = 0; p < 2; p++) {
            u32 off = SW128((u32)((b_n + p * 16) * 128 + ks * 32 + b_kb));
            u32 r0, r1, r2, r3;
            ldsm4(r0, r1, r2, r3, sB + off);
            b4[2 * p][0] = r0; b4[2 * p][1] = r1;
            b4[2 * p + 1][0] = r2; b4[2 * p + 1][1] = r3;
        }
#pragma unroll
        for (int mt = 0; mt < 4; mt++)
#pragma unroll
            for (int nt = 0; nt < 4; nt++)
                mma_f16(acc[mt][nt], a4[mt], b4[nt]);
    }

    const int tm = lane >> 2;
    const int tn = (lane & 3) * 2;
#pragma unroll
    for (int mt = 0; mt < 4; mt++) {
        int gm0 = row0 + wm + mt * 16 + tm;
#pragma unroll
        for (int nt = 0; nt < 4; nt++) {
            int gn = wn + nt * 8 + tn;
            __half2 v01 = __floats2half2_rn(acc[mt][nt][0], acc[mt][nt][1]);
            __half2 v23 = __floats2half2_rn(acc[mt][nt][2], acc[mt][nt][3]);
            if (gm0 < M)     *(__half2*)(Cm + (size_t)gm0 * 128 + gn) = v01;
            if (gm0 + 8 < M) *(__half2*)(Cm + (size_t)(gm0 + 8) * 128 + gn) = v23;
        }
    }
}

// ---------------------------------------------------------------------------
// Layer-1 aggregation (fp16 PG):  h1[n] = relu(P[n] + 0.2 * sum_s G[nb])
// ---------------------------------------------------------------------------
__global__ void aggregate1_kernel(const int* __restrict__ neigh) {
    int gw   = (blockIdx.x * 256 + threadIdx.x) >> 5;
    int lane = threadIdx.x & 31;
    if (gw >= N_NODES) return;

    __half2 s = *(const __half2*)(g_PG + (size_t)gw * 128 + lane * 2);
    float sx = __low2float(s), sy = __high2float(s);
    float ax = 0.f, ay = 0.f;
#pragma unroll
    for (int j = 0; j < NSAMP; j++) {
        int nb = __ldg(&neigh[gw * NSAMP + j]);
        __half2 v = *(const __half2*)(g_PG + (size_t)nb * 128 + 64 + lane * 2);
        ax += __low2float(v); ay += __high2float(v);
    }
    float hx = fmaxf(fmaf(ax, 0.2f, sx), 0.f);
    float hy = fmaxf(fmaf(ay, 0.2f, sy), 0.f);
    *(__half2*)(g_h1 + (size_t)gw * 64 + lane * 2) = __floats2half2_rn(hx, hy);
}

// ---------------------------------------------------------------------------
// Final: h2 = relu(U[n] + 0.2 * sum_s V[nb]); out = h2 @ w_cls.T
// ---------------------------------------------------------------------------
__global__ __launch_bounds__(256)
void final_kernel(const int* __restrict__ nodes, const int* __restrict__ neigh,
                  const float* __restrict__ wcls, float* __restrict__ out) {
    __shared__ float h2s[4][64];
    __shared__ float wcs[16][66];

    int tid = threadIdx.x;
    for (int i = tid; i < NCLS * HIDDEN; i += 256)
        wcs[i >> 6][i & 63] = wcls[i];

    int sub = tid >> 6;
    int h   = tid & 63;
    int b   = blockIdx.x * 4 + sub;

    float val = 0.f;
    if (b < NBATCH) {
        int n = nodes[b];
        float self = __half2float(g_UV[(size_t)n * 128 + h]);
        float acc = 0.f;
#pragma unroll
        for (int j = 0; j < NSAMP; j++) {
            int nb = __ldg(&neigh[n * NSAMP + j]);
            acc += __half2float(g_UV[(size_t)nb * 128 + 64 + h]);
        }
        val = fmaxf(fmaf(acc, 0.2f, self), 0.f);
    }
    h2s[sub][h] = val;
    __syncthreads();

    if (tid < 64) {
        int sub2 = tid >> 4;
        int c    = tid & 15;
        int b2   = blockIdx.x * 4 + sub2;
        if (b2 < NBATCH) {
            float acc = 0.f;
#pragma unroll
            for (int k = 0; k < HIDDEN; k++)
                acc = fmaf(wcs[c][k], h2s[sub2][k], acc);
            out[b2 * NCLS + c] = acc;
        }
    }
}

// ---------------------------------------------------------------------------
extern "C" void kernel_launch(void* const* d_in, const int* in_sizes, int n_in,
                              void* d_out, int out_size) {
    const float* features = (const float*)d_in[0];
    const float* w1       = (const float*)d_in[1];
    const float* w2       = (const float*)d_in[2];
    const float* wcls     = (const float*)d_in[3];
    const int*   nodes    = (const int*)d_in[4];
    const int*   neigh    = (const int*)d_in[5];
    float*       out      = (float*)d_out;

    __half *pW1, *pW2, *ph1, *pPG, *pUV;
    cudaGetSymbolAddress((void**)&pW1, g_W1);
    cudaGetSymbolAddress((void**)&pW2, g_W2);
    cudaGetSymbolAddress((void**)&ph1, g_h1);
    cudaGetSymbolAddress((void**)&pPG, g_PG);
    cudaGetSymbolAddress((void**)&pUV, g_UV);

    cudaFuncSetAttribute(gemm1_tc, cudaFuncAttributeMaxDynamicSharedMemorySize, G1_SMEM);
    cudaFuncSetAttribute(gemm2_tc, cudaFuncAttributeMaxDynamicSharedMemorySize, 2 * G2_BUF);

    const int gemm_blocks = (N_NODES + 127) / 128;   // 782

    prep_weights<<<(128 * N_FEATS + 255) / 256, 256>>>(w1, w2);
    gemm1_tc<<<gemm_blocks, 256, G1_SMEM>>>(features, pW1, pPG, N_NODES);
    aggregate1_kernel<<<(N_NODES * 32 + 255) / 256, 256>>>(neigh);
    gemm2_tc<<<gemm_blocks, 256, 2 * G2_BUF>>>(ph1, pW2, pUV, N_NODES);
    final_kernel<<<(NBATCH + 3) / 4, 256>>>(nodes, neigh, wcls, out);
}

// round 8
// speedup vs baseline: 3.5247x; 1.0918x over previous
#include <cuda_runtime.h>
#include <cuda_fp16.h>

#define N_NODES 100000
#define N_FEATS 512
#define HIDDEN  64
#define NSAMP   5
#define NCLS    16
#define NBATCH  16384

typedef unsigned int u32;

// ---------------- scratch (static device globals) ---------------------------
__device__ __half g_W1[128 * N_FEATS];   // [n=0..127][k] row-major fp16
__device__ __half g_W2[128 * HIDDEN];
__device__ __half g_PG[(size_t)N_NODES * 128];      // P | G  (fp16)
__device__ __half g_UV[(size_t)N_NODES * 128];      // U | V  (fp16)

// ---------------- helpers ----------------------------------------------------
__device__ __forceinline__ u32 smem_u32(const void* p) {
    u32 a;
    asm("{ .reg .u64 t; cvta.to.shared.u64 t, %1; cvt.u32.u64 %0, t; }"
        : "=r"(a) : "l"(p));
    return a;
}
__device__ __forceinline__ void ldsm4(u32& r0, u32& r1, u32& r2, u32& r3, u32 addr) {
    asm volatile("ldmatrix.sync.aligned.m8n8.x4.shared.b16 {%0,%1,%2,%3}, [%4];"
                 : "=r"(r0), "=r"(r1), "=r"(r2), "=r"(r3) : "r"(addr));
}
__device__ __forceinline__ void mma_f16(float* d, const u32* a, const u32* b) {
    asm volatile(
        "mma.sync.aligned.m16n8k16.row.col.f32.f16.f16.f32 "
        "{%0,%1,%2,%3}, {%4,%5,%6,%7}, {%8,%9}, {%0,%1,%2,%3};"
        : "+f"(d[0]), "+f"(d[1]), "+f"(d[2]), "+f"(d[3])
        : "r"(a[0]), "r"(a[1]), "r"(a[2]), "r"(a[3]), "r"(b[0]), "r"(b[1]));
}
__device__ __forceinline__ void cpasync16(u32 dst, const void* src, int srcsize) {
    asm volatile("cp.async.cg.shared.global [%0], [%1], 16, %2;"
                 :: "r"(dst), "l"(src), "r"(srcsize) : "memory");
}
__device__ __forceinline__ void cpcommit() {
    asm volatile("cp.async.commit_group;" ::: "memory");
}
template <int N>
__device__ __forceinline__ void cpwait() {
    asm volatile("cp.async.wait_group %0;" :: "n"(N) : "memory");
}
#define SW128(x) ((x) ^ (((x) >> 3) & 0x70))
#define SW64(x)  ((x) ^ (((x) >> 3) & 0x30))

// ---------------------------------------------------------------------------
// Weight prep: round fp32 weights to fp16, [n=0..127][k] row-major
// (n<64 -> self block, n>=64 -> neighbor block).
// ---------------------------------------------------------------------------
__global__ void prep_weights(const float* __restrict__ w1, const float* __restrict__ w2) {
    int idx = blockIdx.x * 256 + threadIdx.x;
    if (idx < 128 * N_FEATS) {
        int n = idx / N_FEATS, k = idx % N_FEATS;
        float v = (n < 64) ? w1[n * (2 * N_FEATS) + k]
                           : w1[(n - 64) * (2 * N_FEATS) + N_FEATS + k];
        g_W1[idx] = __float2half_rn(v);
    }
    if (idx < 128 * HIDDEN) {
        int n = idx / HIDDEN, k = idx % HIDDEN;
        float v = (n < 64) ? w2[n * (2 * HIDDEN) + k]
                           : w2[(n - 64) * (2 * HIDDEN) + HIDDEN + k];
        g_W2[idx] = __float2half_rn(v);
    }
}

// ===========================================================================
// GEMM1: C[M,128] (fp16) = A[M,512] (fp32, converted in smem) @ W1[128,512]^T
// 128x128 CTA tile, 8 warps (64x32 warp tiles), KC=32.
// Ring: 3 A-fp32 stages (16KB), 4 B-fp16 stages (8KB), 2 fp16 work bufs (8KB).
// One __syncthreads per chunk; convert(t+1) overlaps MMA(t).
// ===========================================================================
#define KC1   32
#define NCH1  (N_FEATS / KC1)          // 16
#define A1_OFF   0                      // 3 x 16384
#define A1_BYTES 16384
#define B1_OFF   49152                  // 4 x 8192
#define B1_BYTES 8192
#define W1_OFF   81920                  // 2 x 8192
#define W1_BYTES 8192
#define G1_SMEM  98304                  // 96 KB

__global__ __launch_bounds__(256, 2)
void gemm1_tc(const float* __restrict__ Af, const __half* __restrict__ Bm,
              __half* __restrict__ Cm, int M) {
    extern __shared__ __align__(1024) char smem[];
    const u32 sb = smem_u32(smem);
    const int tid  = threadIdx.x;
    const int wid  = tid >> 5;
    const int lane = tid & 31;
    const int wm   = (wid & 1) * 64;
    const int wn   = (wid >> 1) * 32;
    const int row0 = blockIdx.x * 128;

    const int lrow  = tid >> 1;        // 0..127
    const int lhalf = tid & 1;
    const bool arow_ok = (row0 + lrow) < M;
    const u32 aoff = (u32)lrow * 128 + (u32)lhalf * 64;   // A stage byte offset
    const u32 woff = (u32)lrow * 64 + (u32)lhalf * 32;    // fp16 row byte offset

    auto issue_stage = [&](int c) {
        u32 abase = sb + A1_OFF + (c % 3) * A1_BYTES;
        u32 bbase = sb + B1_OFF + (c & 3) * B1_BYTES;
        int k0 = c * KC1;
        const float* asrc = Af + (size_t)(arow_ok ? row0 + lrow : 0) * N_FEATS
                               + k0 + lhalf * 16;
        int sz = arow_ok ? 16 : 0;
#pragma unroll
        for (int j = 0; j < 4; j++)
            cpasync16(abase + SW128(aoff + j * 16), asrc + j * 4, sz);
        const __half* bsrc = Bm + (size_t)lrow * N_FEATS + k0 + lhalf * 16;
#pragma unroll
        for (int j = 0; j < 2; j++)
            cpasync16(bbase + SW64(woff + j * 16), bsrc + j * 8, 16);
        cpcommit();
    };

    auto convert = [&](int c) {
        char* astage = smem + A1_OFF + (c % 3) * A1_BYTES;
        char* wbase  = smem + W1_OFF + (c & 1) * W1_BYTES;
#pragma unroll
        for (int j = 0; j < 2; j++) {
            float4 v0 = *(const float4*)(astage + SW128(aoff + j * 32));
            float4 v1 = *(const float4*)(astage + SW128(aoff + j * 32 + 16));
            __half2 p0 = __floats2half2_rn(v0.x, v0.y);
            __half2 p1 = __floats2half2_rn(v0.z, v0.w);
            __half2 p2 = __floats2half2_rn(v1.x, v1.y);
            __half2 p3 = __floats2half2_rn(v1.z, v1.w);
            *(uint4*)(wbase + SW64(woff + j * 16)) =
                make_uint4(*(u32*)&p0, *(u32*)&p1, *(u32*)&p2, *(u32*)&p3);
        }
    };

    // ldmatrix lane coords
    const int grp = lane >> 3, lr = lane & 7;
    const int a_m  = wm + (grp & 1) * 8 + lr;
    const int a_kb = (grp >> 1) * 16;
    const int b_n  = wn + (grp >> 1) * 8 + lr;
    const int b_kb = (grp & 1) * 16;

    float acc[4][4][4];
#pragma unroll
    for (int i = 0; i < 4; i++)
#pragma unroll
        for (int j = 0; j < 4; j++)
#pragma unroll
            for (int c = 0; c < 4; c++) acc[i][j][c] = 0.f;

    issue_stage(0);
    issue_stage(1);
    issue_stage(2);
    cpwait<2>();          // chunk 0 arrived (own-thread region -> visible)
    convert(0);           // wrk0 <- chunk 0

    for (int t = 0; t < NCH1; ++t) {
        __syncthreads();  // publish wrk[t&1] + B[t]; all reads of t-1 done

        if (t + 3 < NCH1) issue_stage(t + 3);

        // ensure chunk t+1's A (and B) arrived before converting it
        if (t + 3 < NCH1)      cpwait<2>();
        else if (t + 2 < NCH1) cpwait<1>();
        else                   cpwait<0>();

        if (t + 1 < NCH1) convert(t + 1);   // overlaps MMA(t): disjoint buffers

        u32 sW = sb + W1_OFF + (t & 1) * W1_BYTES;
        u32 sB = sb + B1_OFF + (t & 3) * B1_BYTES;

#pragma unroll
        for (int ks = 0; ks < 2; ks++) {
            u32 a4[4][4];
#pragma unroll
            for (int mt = 0; mt < 4; mt++) {
                u32 off = SW64((u32)((a_m + mt * 16) * 64 + ks * 32 + a_kb));
                ldsm4(a4[mt][0], a4[mt][1], a4[mt][2], a4[mt][3], sW + off);
            }
            u32 b4[4][2];
#pragma unroll
            for (int p = 0; p < 2; p++) {
                u32 off = SW64((u32)((b_n + p * 16) * 64 + ks * 32 + b_kb));
                u32 r0, r1, r2, r3;
                ldsm4(r0, r1, r2, r3, sB + off);
                b4[2 * p][0] = r0; b4[2 * p][1] = r1;
                b4[2 * p + 1][0] = r2; b4[2 * p + 1][1] = r3;
            }
#pragma unroll
            for (int mt = 0; mt < 4; mt++)
#pragma unroll
                for (int nt = 0; nt < 4; nt++)
                    mma_f16(acc[mt][nt], a4[mt], b4[nt]);
        }
    }

    // epilogue: fp16 output
    const int tm = lane >> 2;
    const int tn = (lane & 3) * 2;
#pragma unroll
    for (int mt = 0; mt < 4; mt++) {
        int gm0 = row0 + wm + mt * 16 + tm;
#pragma unroll
        for (int nt = 0; nt < 4; nt++) {
            int gn = wn + nt * 8 + tn;
            __half2 v01 = __floats2half2_rn(acc[mt][nt][0], acc[mt][nt][1]);
            __half2 v23 = __floats2half2_rn(acc[mt][nt][2], acc[mt][nt][3]);
            if (gm0 < M)     *(__half2*)(Cm + (size_t)gm0 * 128 + gn) = v01;
            if (gm0 + 8 < M) *(__half2*)(Cm + (size_t)(gm0 + 8) * 128 + gn) = v23;
        }
    }
}

// ===========================================================================
// GEMM2 fused with layer-1 aggregation:
//   A[r] = relu(P[n] + 0.2 * sum_s G[neigh[n,s]])  built in smem from g_PG,
//   C[M,128] (fp16) = A[M,64] @ W2[128,64]^T.
// ===========================================================================
#define G2_OFFA 0
#define G2_OFFB 16384
#define G2_SMEM 32768

__global__ __launch_bounds__(256, 2)
void gemm2_fused(const int* __restrict__ neigh, const __half* __restrict__ Bm,
                 __half* __restrict__ Cm, int M) {
    extern __shared__ __align__(1024) char smem[];
    const u32 sb = smem_u32(smem);
    const int tid  = threadIdx.x;
    const int wid  = tid >> 5;
    const int lane = tid & 31;
    const int wm   = (wid & 1) * 64;
    const int wn   = (wid >> 1) * 32;
    const int row0 = blockIdx.x * 128;

    const int lrow  = tid >> 1;
    const int lhalf = tid & 1;
    const u32 rowoff = (u32)lrow * 128 + (u32)lhalf * 64;
    const int n = row0 + lrow;
    const bool arow_ok = n < M;

    // --- B tile via cp.async (issue first so it overlaps the gather) ---
    {
        u32 bbase = sb + G2_OFFB;
        const __half* bsrc = Bm + (size_t)lrow * HIDDEN + lhalf * 32;
#pragma unroll
        for (int j = 0; j < 4; j++)
            cpasync16(bbase + SW128(rowoff + j * 16), bsrc + j * 8, 16);
        cpcommit();
    }

    // --- A tile: fused aggregation from g_PG (L2-resident) ---
    {
        float val[32];
#pragma unroll
        for (int e = 0; e < 32; e++) val[e] = 0.f;

        if (arow_ok) {
            // sum of 5 neighbor G halves
#pragma unroll
            for (int s = 0; s < NSAMP; s++) {
                int nb = __ldg(&neigh[n * NSAMP + s]);
                const uint4* src = (const uint4*)(g_PG + (size_t)nb * 128 + 64 + lhalf * 32);
#pragma unroll
                for (int j = 0; j < 4; j++) {
                    uint4 v = __ldg(src + j);
                    u32 w[4] = {v.x, v.y, v.z, v.w};
#pragma unroll
                    for (int q = 0; q < 4; q++) {
                        __half2 h = *(__half2*)&w[q];
                        val[j * 8 + q * 2]     += __low2float(h);
                        val[j * 8 + q * 2 + 1] += __high2float(h);
                    }
                }
            }
            // self P half + relu
            const uint4* sp = (const uint4*)(g_PG + (size_t)n * 128 + lhalf * 32);
#pragma unroll
            for (int j = 0; j < 4; j++) {
                uint4 v = __ldg(sp + j);
                u32 w[4] = {v.x, v.y, v.z, v.w};
#pragma unroll
                for (int q = 0; q < 4; q++) {
                    __half2 h = *(__half2*)&w[q];
                    int e = j * 8 + q * 2;
                    val[e]     = fmaxf(fmaf(val[e],     0.2f, __low2float(h)),  0.f);
                    val[e + 1] = fmaxf(fmaf(val[e + 1], 0.2f, __high2float(h)), 0.f);
                }
            }
        }

        char* abase = smem + G2_OFFA;
#pragma unroll
        for (int j = 0; j < 4; j++) {
            __half2 p0 = __floats2half2_rn(val[j * 8 + 0], val[j * 8 + 1]);
            __half2 p1 = __floats2half2_rn(val[j * 8 + 2], val[j * 8 + 3]);
            __half2 p2 = __floats2half2_rn(val[j * 8 + 4], val[j * 8 + 5]);
            __half2 p3 = __floats2half2_rn(val[j * 8 + 6], val[j * 8 + 7]);
            *(uint4*)(abase + SW128(rowoff + j * 16)) =
                make_uint4(*(u32*)&p0, *(u32*)&p1, *(u32*)&p2, *(u32*)&p3);
        }
    }

    cpwait<0>();
    __syncthreads();

    const int grp = lane >> 3, lr = lane & 7;
    const int a_m  = wm + (grp & 1) * 8 + lr;
    const int a_kb = (grp >> 1) * 16;
    const int b_n  = wn + (grp >> 1) * 8 + lr;
    const int b_kb = (grp & 1) * 16;

    float acc[4][4][4];
#pragma unroll
    for (int i = 0; i < 4; i++)
#pragma unroll
        for (int j = 0; j < 4; j++)
#pragma unroll
            for (int c = 0; c < 4; c++) acc[i][j][c] = 0.f;

    u32 sA = sb + G2_OFFA, sB = sb + G2_OFFB;
#pragma unroll
    for (int ks = 0; ks < 4; ks++) {
        u32 a4[4][4];
#pragma unroll
        for (int mt = 0; mt < 4; mt++) {
            u32 off = SW128((u32)((a_m + mt * 16) * 128 + ks * 32 + a_kb));
            ldsm4(a4[mt][0], a4[mt][1], a4[mt][2], a4[mt][3], sA + off);
        }
        u32 b4[4][2];
#pragma unroll
        for (int p = 0; p < 2; p++) {
            u32 off = SW128((u32)((b_n + p * 16) * 128 + ks * 32 + b_kb));
            u32 r0, r1, r2, r3;
            ldsm4(r0, r1, r2, r3, sB + off);
            b4[2 * p][0] = r0; b4[2 * p][1] = r1;
            b4[2 * p + 1][0] = r2; b4[2 * p + 1][1] = r3;
        }
#pragma unroll
        for (int mt = 0; mt < 4; mt++)
#pragma unroll
            for (int nt = 0; nt < 4; nt++)
                mma_f16(acc[mt][nt], a4[mt], b4[nt]);
    }

    const int tm = lane >> 2;
    const int tn = (lane & 3) * 2;
#pragma unroll
    for (int mt = 0; mt < 4; mt++) {
        int gm0 = row0 + wm + mt * 16 + tm;
#pragma unroll
        for (int nt = 0; nt < 4; nt++) {
            int gn = wn + nt * 8 + tn;
            __half2 v01 = __floats2half2_rn(acc[mt][nt][0], acc[mt][nt][1]);
            __half2 v23 = __floats2half2_rn(acc[mt][nt][2], acc[mt][nt][3]);
            if (gm0 < M)     *(__half2*)(Cm + (size_t)gm0 * 128 + gn) = v01;
            if (gm0 + 8 < M) *(__half2*)(Cm + (size_t)(gm0 + 8) * 128 + gn) = v23;
        }
    }
}

// ---------------------------------------------------------------------------
// Final: h2 = relu(U[n] + 0.2 * sum_s V[nb]); out = h2 @ w_cls.T
// ---------------------------------------------------------------------------
__global__ __launch_bounds__(256)
void final_kernel(const int* __restrict__ nodes, const int* __restrict__ neigh,
                  const float* __restrict__ wcls, float* __restrict__ out) {
    __shared__ float h2s[4][64];
    __shared__ float wcs[16][66];

    int tid = threadIdx.x;
    for (int i = tid; i < NCLS * HIDDEN; i += 256)
        wcs[i >> 6][i & 63] = wcls[i];

    int sub = tid >> 6;
    int h   = tid & 63;
    int b   = blockIdx.x * 4 + sub;

    float val = 0.f;
    if (b < NBATCH) {
        int n = nodes[b];
        float self = __half2float(g_UV[(size_t)n * 128 + h]);
        float acc = 0.f;
#pragma unroll
        for (int j = 0; j < NSAMP; j++) {
            int nb = __ldg(&neigh[n * NSAMP + j]);
            acc += __half2float(g_UV[(size_t)nb * 128 + 64 + h]);
        }
        val = fmaxf(fmaf(acc, 0.2f, self), 0.f);
    }
    h2s[sub][h] = val;
    __syncthreads();

    if (tid < 64) {
        int sub2 = tid >> 4;
        int c    = tid & 15;
        int b2   = blockIdx.x * 4 + sub2;
        if (b2 < NBATCH) {
            float acc = 0.f;
#pragma unroll
            for (int k = 0; k < HIDDEN; k++)
                acc = fmaf(wcs[c][k], h2s[sub2][k], acc);
            out[b2 * NCLS + c] = acc;
        }
    }
}

// ---------------------------------------------------------------------------
extern "C" void kernel_launch(void* const* d_in, const int* in_sizes, int n_in,
                              void* d_out, int out_size) {
    const float* features = (const float*)d_in[0];
    const float* w1       = (const float*)d_in[1];
    const float* w2       = (const float*)d_in[2];
    const float* wcls     = (const float*)d_in[3];
    const int*   nodes    = (const int*)d_in[4];
    const int*   neigh    = (const int*)d_in[5];
    float*       out      = (float*)d_out;

    __half *pW1, *pW2, *pPG, *pUV;
    cudaGetSymbolAddress((void**)&pW1, g_W1);
    cudaGetSymbolAddress((void**)&pW2, g_W2);
    cudaGetSymbolAddress((void**)&pPG, g_PG);
    cudaGetSymbolAddress((void**)&pUV, g_UV);

    cudaFuncSetAttribute(gemm1_tc, cudaFuncAttributeMaxDynamicSharedMemorySize, G1_SMEM);
    cudaFuncSetAttribute(gemm2_fused, cudaFuncAttributeMaxDynamicSharedMemorySize, G2_SMEM);

    const int gemm_blocks = (N_NODES + 127) / 128;   // 782

    prep_weights<<<(128 * N_FEATS + 255) / 256, 256>>>(w1, w2);
    gemm1_tc<<<gemm_blocks, 256, G1_SMEM>>>(features, pW1, pPG, N_NODES);
    gemm2_fused<<<gemm_blocks, 256, G2_SMEM>>>(neigh, pW2, pUV, N_NODES);
    final_kernel<<<(NBATCH + 3) / 4, 256>>>(nodes, neigh, wcls, out);
}

// round 9
// speedup vs baseline: 3.7203x; 1.0555x over previous
#include <cuda_runtime.h>
#include <cuda_fp16.h>

#define N_NODES 100000
#define N_FEATS 512
#define HIDDEN  64
#define NSAMP   5
#define NCLS    16
#define NBATCH  16384

typedef unsigned int u32;

// ---------------- scratch (static device globals) ---------------------------
__device__ __half g_W1[128 * N_FEATS];   // [n=0..127][k] row-major fp16
__device__ __half g_W2[128 * HIDDEN];
__device__ __half g_Wc[32 * HIDDEN];     // rows 0-15: wcls hi, rows 16-31: wcls lo
__device__ __half g_PG[(size_t)N_NODES * 128];      // P | G  (fp16)
__device__ __half g_UV[(size_t)N_NODES * 128];      // U | V  (fp16)

// ---------------- helpers ----------------------------------------------------
__device__ __forceinline__ u32 smem_u32(const void* p) {
    u32 a;
    asm("{ .reg .u64 t; cvta.to.shared.u64 t, %1; cvt.u32.u64 %0, t; }"
        : "=r"(a) : "l"(p));
    return a;
}
__device__ __forceinline__ void ldsm4(u32& r0, u32& r1, u32& r2, u32& r3, u32 addr) {
    asm volatile("ldmatrix.sync.aligned.m8n8.x4.shared.b16 {%0,%1,%2,%3}, [%4];"
                 : "=r"(r0), "=r"(r1), "=r"(r2), "=r"(r3) : "r"(addr));
}
__device__ __forceinline__ void mma_f16(float* d, const u32* a, const u32* b) {
    asm volatile(
        "mma.sync.aligned.m16n8k16.row.col.f32.f16.f16.f32 "
        "{%0,%1,%2,%3}, {%4,%5,%6,%7}, {%8,%9}, {%0,%1,%2,%3};"
        : "+f"(d[0]), "+f"(d[1]), "+f"(d[2]), "+f"(d[3])
        : "r"(a[0]), "r"(a[1]), "r"(a[2]), "r"(a[3]), "r"(b[0]), "r"(b[1]));
}
__device__ __forceinline__ void cpasync16(u32 dst, const void* src, int srcsize) {
    asm volatile("cp.async.cg.shared.global [%0], [%1], 16, %2;"
                 :: "r"(dst), "l"(src), "r"(srcsize) : "memory");
}
__device__ __forceinline__ void cpcommit() {
    asm volatile("cp.async.commit_group;" ::: "memory");
}
template <int N>
__device__ __forceinline__ void cpwait() {
    asm volatile("cp.async.wait_group %0;" :: "n"(N) : "memory");
}
#define SW128(x) ((x) ^ (((x) >> 3) & 0x70))
#define SW64(x)  ((x) ^ (((x) >> 3) & 0x30))

// ---------------------------------------------------------------------------
// Weight prep: W1/W2 fp16 ([n][k] row-major; n<64 self, n>=64 neighbor block),
// wcls split into fp16 hi/lo rows.
// ---------------------------------------------------------------------------
__global__ void prep_weights(const float* __restrict__ w1, const float* __restrict__ w2,
                             const float* __restrict__ wcls) {
    int idx = blockIdx.x * 256 + threadIdx.x;
    if (idx < 128 * N_FEATS) {
        int n = idx / N_FEATS, k = idx % N_FEATS;
        float v = (n < 64) ? w1[n * (2 * N_FEATS) + k]
                           : w1[(n - 64) * (2 * N_FEATS) + N_FEATS + k];
        g_W1[idx] = __float2half_rn(v);
    }
    if (idx < 128 * HIDDEN) {
        int n = idx / HIDDEN, k = idx % HIDDEN;
        float v = (n < 64) ? w2[n * (2 * HIDDEN) + k]
                           : w2[(n - 64) * (2 * HIDDEN) + HIDDEN + k];
        g_W2[idx] = __float2half_rn(v);
    }
    if (idx < NCLS * HIDDEN) {
        float v = wcls[idx];
        __half h = __float2half_rn(v);
        g_Wc[idx] = h;
        g_Wc[NCLS * HIDDEN + idx] = __float2half_rn(v - __half2float(h));
    }
}

// ===========================================================================
// GEMM1: C[M,128] (fp16) = A[M,512] (fp32, converted in smem) @ W1[128,512]^T
// 128x128 CTA tile, 8 warps (64x32 warp tiles), KC=32.
// Ring: 3 A-fp32 stages (16KB), 4 B-fp16 stages (8KB), 2 fp16 work bufs (8KB).
// One __syncthreads per chunk; convert(t+1) overlaps MMA(t).
// ===========================================================================
#define KC1   32
#define NCH1  (N_FEATS / KC1)          // 16
#define A1_OFF   0                      // 3 x 16384
#define A1_BYTES 16384
#define B1_OFF   49152                  // 4 x 8192
#define B1_BYTES 8192
#define W1_OFF   81920                  // 2 x 8192
#define W1_BYTES 8192
#define G1_SMEM  98304                  // 96 KB

__global__ __launch_bounds__(256, 2)
void gemm1_tc(const float* __restrict__ Af, const __half* __restrict__ Bm,
              __half* __restrict__ Cm, int M) {
    extern __shared__ __align__(1024) char smem[];
    const u32 sb = smem_u32(smem);
    const int tid  = threadIdx.x;
    const int wid  = tid >> 5;
    const int lane = tid & 31;
    const int wm   = (wid & 1) * 64;
    const int wn   = (wid >> 1) * 32;
    const int row0 = blockIdx.x * 128;

    const int lrow  = tid >> 1;        // 0..127
    const int lhalf = tid & 1;
    const bool arow_ok = (row0 + lrow) < M;
    const u32 aoff = (u32)lrow * 128 + (u32)lhalf * 64;   // A stage byte offset
    const u32 woff = (u32)lrow * 64 + (u32)lhalf * 32;    // fp16 row byte offset

    auto issue_stage = [&](int c) {
        u32 abase = sb + A1_OFF + (c % 3) * A1_BYTES;
        u32 bbase = sb + B1_OFF + (c & 3) * B1_BYTES;
        int k0 = c * KC1;
        const float* asrc = Af + (size_t)(arow_ok ? row0 + lrow : 0) * N_FEATS
                               + k0 + lhalf * 16;
        int sz = arow_ok ? 16 : 0;
#pragma unroll
        for (int j = 0; j < 4; j++)
            cpasync16(abase + SW128(aoff + j * 16), asrc + j * 4, sz);
        const __half* bsrc = Bm + (size_t)lrow * N_FEATS + k0 + lhalf * 16;
#pragma unroll
        for (int j = 0; j < 2; j++)
            cpasync16(bbase + SW64(woff + j * 16), bsrc + j * 8, 16);
        cpcommit();
    };

    auto convert = [&](int c) {
        char* astage = smem + A1_OFF + (c % 3) * A1_BYTES;
        char* wbase  = smem + W1_OFF + (c & 1) * W1_BYTES;
#pragma unroll
        for (int j = 0; j < 2; j++) {
            float4 v0 = *(const float4*)(astage + SW128(aoff + j * 32));
            float4 v1 = *(const float4*)(astage + SW128(aoff + j * 32 + 16));
            __half2 p0 = __floats2half2_rn(v0.x, v0.y);
            __half2 p1 = __floats2half2_rn(v0.z, v0.w);
            __half2 p2 = __floats2half2_rn(v1.x, v1.y);
            __half2 p3 = __floats2half2_rn(v1.z, v1.w);
            *(uint4*)(wbase + SW64(woff + j * 16)) =
                make_uint4(*(u32*)&p0, *(u32*)&p1, *(u32*)&p2, *(u32*)&p3);
        }
    };

    // ldmatrix lane coords
    const int grp = lane >> 3, lr = lane & 7;
    const int a_m  = wm + (grp & 1) * 8 + lr;
    const int a_kb = (grp >> 1) * 16;
    const int b_n  = wn + (grp >> 1) * 8 + lr;
    const int b_kb = (grp & 1) * 16;

    float acc[4][4][4];
#pragma unroll
    for (int i = 0; i < 4; i++)
#pragma unroll
        for (int j = 0; j < 4; j++)
#pragma unroll
            for (int c = 0; c < 4; c++) acc[i][j][c] = 0.f;

    issue_stage(0);
    issue_stage(1);
    issue_stage(2);
    cpwait<2>();          // chunk 0 arrived
    convert(0);

    for (int t = 0; t < NCH1; ++t) {
        __syncthreads();  // publish wrk[t&1] + B[t]; all reads of t-1 done

        if (t + 3 < NCH1) issue_stage(t + 3);

        if (t + 3 < NCH1)      cpwait<2>();
        else if (t + 2 < NCH1) cpwait<1>();
        else                   cpwait<0>();

        if (t + 1 < NCH1) convert(t + 1);   // overlaps MMA(t)

        u32 sW = sb + W1_OFF + (t & 1) * W1_BYTES;
        u32 sB = sb + B1_OFF + (t & 3) * B1_BYTES;

#pragma unroll
        for (int ks = 0; ks < 2; ks++) {
            u32 a4[4][4];
#pragma unroll
            for (int mt = 0; mt < 4; mt++) {
                u32 off = SW64((u32)((a_m + mt * 16) * 64 + ks * 32 + a_kb));
                ldsm4(a4[mt][0], a4[mt][1], a4[mt][2], a4[mt][3], sW + off);
            }
            u32 b4[4][2];
#pragma unroll
            for (int p = 0; p < 2; p++) {
                u32 off = SW64((u32)((b_n + p * 16) * 64 + ks * 32 + b_kb));
                u32 r0, r1, r2, r3;
                ldsm4(r0, r1, r2, r3, sB + off);
                b4[2 * p][0] = r0; b4[2 * p][1] = r1;
                b4[2 * p + 1][0] = r2; b4[2 * p + 1][1] = r3;
            }
#pragma unroll
            for (int mt = 0; mt < 4; mt++)
#pragma unroll
                for (int nt = 0; nt < 4; nt++)
                    mma_f16(acc[mt][nt], a4[mt], b4[nt]);
        }
    }

    // epilogue: fp16 output
    const int tm = lane >> 2;
    const int tn = (lane & 3) * 2;
#pragma unroll
    for (int mt = 0; mt < 4; mt++) {
        int gm0 = row0 + wm + mt * 16 + tm;
#pragma unroll
        for (int nt = 0; nt < 4; nt++) {
            int gn = wn + nt * 8 + tn;
            __half2 v01 = __floats2half2_rn(acc[mt][nt][0], acc[mt][nt][1]);
            __half2 v23 = __floats2half2_rn(acc[mt][nt][2], acc[mt][nt][3]);
            if (gm0 < M)     *(__half2*)(Cm + (size_t)gm0 * 128 + gn) = v01;
            if (gm0 + 8 < M) *(__half2*)(Cm + (size_t)(gm0 + 8) * 128 + gn) = v23;
        }
    }
}

// ===========================================================================
// GEMM2 fused with layer-1 aggregation:
//   A[r] = relu(P[n] + 0.2 * sum_s G[neigh[n,s]])  built in smem from g_PG,
//   C[M,128] (fp16) = A[M,64] @ W2[128,64]^T.
// ===========================================================================
#define G2_OFFA 0
#define G2_OFFB 16384
#define G2_SMEM 32768

__global__ __launch_bounds__(256, 2)
void gemm2_fused(const int* __restrict__ neigh, const __half* __restrict__ Bm,
                 __half* __restrict__ Cm, int M) {
    extern __shared__ __align__(1024) char smem[];
    const u32 sb = smem_u32(smem);
    const int tid  = threadIdx.x;
    const int wid  = tid >> 5;
    const int lane = tid & 31;
    const int wm   = (wid & 1) * 64;
    const int wn   = (wid >> 1) * 32;
    const int row0 = blockIdx.x * 128;

    const int lrow  = tid >> 1;
    const int lhalf = tid & 1;
    const u32 rowoff = (u32)lrow * 128 + (u32)lhalf * 64;
    const int n = row0 + lrow;
    const bool arow_ok = n < M;

    // --- B tile via cp.async (overlaps the gather) ---
    {
        u32 bbase = sb + G2_OFFB;
        const __half* bsrc = Bm + (size_t)lrow * HIDDEN + lhalf * 32;
#pragma unroll
        for (int j = 0; j < 4; j++)
            cpasync16(bbase + SW128(rowoff + j * 16), bsrc + j * 8, 16);
        cpcommit();
    }

    // --- A tile: fused aggregation from g_PG (L2-resident) ---
    {
        float val[32];
#pragma unroll
        for (int e = 0; e < 32; e++) val[e] = 0.f;

        if (arow_ok) {
#pragma unroll
            for (int s = 0; s < NSAMP; s++) {
                int nb = __ldg(&neigh[n * NSAMP + s]);
                const uint4* src = (const uint4*)(g_PG + (size_t)nb * 128 + 64 + lhalf * 32);
#pragma unroll
                for (int j = 0; j < 4; j++) {
                    uint4 v = __ldg(src + j);
                    u32 w[4] = {v.x, v.y, v.z, v.w};
#pragma unroll
                    for (int q = 0; q < 4; q++) {
                        __half2 h = *(__half2*)&w[q];
                        val[j * 8 + q * 2]     += __low2float(h);
                        val[j * 8 + q * 2 + 1] += __high2float(h);
                    }
                }
            }
            const uint4* sp = (const uint4*)(g_PG + (size_t)n * 128 + lhalf * 32);
#pragma unroll
            for (int j = 0; j < 4; j++) {
                uint4 v = __ldg(sp + j);
                u32 w[4] = {v.x, v.y, v.z, v.w};
#pragma unroll
                for (int q = 0; q < 4; q++) {
                    __half2 h = *(__half2*)&w[q];
                    int e = j * 8 + q * 2;
                    val[e]     = fmaxf(fmaf(val[e],     0.2f, __low2float(h)),  0.f);
                    val[e + 1] = fmaxf(fmaf(val[e + 1], 0.2f, __high2float(h)), 0.f);
                }
            }
        }

        char* abase = smem + G2_OFFA;
#pragma unroll
        for (int j = 0; j < 4; j++) {
            __half2 p0 = __floats2half2_rn(val[j * 8 + 0], val[j * 8 + 1]);
            __half2 p1 = __floats2half2_rn(val[j * 8 + 2], val[j * 8 + 3]);
            __half2 p2 = __floats2half2_rn(val[j * 8 + 4], val[j * 8 + 5]);
            __half2 p3 = __floats2half2_rn(val[j * 8 + 6], val[j * 8 + 7]);
            *(uint4*)(abase + SW128(rowoff + j * 16)) =
                make_uint4(*(u32*)&p0, *(u32*)&p1, *(u32*)&p2, *(u32*)&p3);
        }
    }

    cpwait<0>();
    __syncthreads();

    const int grp = lane >> 3, lr = lane & 7;
    const int a_m  = wm + (grp & 1) * 8 + lr;
    const int a_kb = (grp >> 1) * 16;
    const int b_n  = wn + (grp >> 1) * 8 + lr;
    const int b_kb = (grp & 1) * 16;

    float acc[4][4][4];
#pragma unroll
    for (int i = 0; i < 4; i++)
#pragma unroll
        for (int j = 0; j < 4; j++)
#pragma unroll
            for (int c = 0; c < 4; c++) acc[i][j][c] = 0.f;

    u32 sA = sb + G2_OFFA, sB = sb + G2_OFFB;
#pragma unroll
    for (int ks = 0; ks < 4; ks++) {
        u32 a4[4][4];
#pragma unroll
        for (int mt = 0; mt < 4; mt++) {
            u32 off = SW128((u32)((a_m + mt * 16) * 128 + ks * 32 + a_kb));
            ldsm4(a4[mt][0], a4[mt][1], a4[mt][2], a4[mt][3], sA + off);
        }
        u32 b4[4][2];
#pragma unroll
        for (int p = 0; p < 2; p++) {
            u32 off = SW128((u32)((b_n + p * 16) * 128 + ks * 32 + b_kb));
            u32 r0, r1, r2, r3;
            ldsm4(r0, r1, r2, r3, sB + off);
            b4[2 * p][0] = r0; b4[2 * p][1] = r1;
            b4[2 * p + 1][0] = r2; b4[2 * p + 1][1] = r3;
        }
#pragma unroll
        for (int mt = 0; mt < 4; mt++)
#pragma unroll
            for (int nt = 0; nt < 4; nt++)
                mma_f16(acc[mt][nt], a4[mt], b4[nt]);
    }

    const int tm = lane >> 2;
    const int tn = (lane & 3) * 2;
#pragma unroll
    for (int mt = 0; mt < 4; mt++) {
        int gm0 = row0 + wm + mt * 16 + tm;
#pragma unroll
        for (int nt = 0; nt < 4; nt++) {
            int gn = wn + nt * 8 + tn;
            __half2 v01 = __floats2half2_rn(acc[mt][nt][0], acc[mt][nt][1]);
            __half2 v23 = __floats2half2_rn(acc[mt][nt][2], acc[mt][nt][3]);
            if (gm0 < M)     *(__half2*)(Cm + (size_t)gm0 * 128 + gn) = v01;
            if (gm0 + 8 < M) *(__half2*)(Cm + (size_t)(gm0 + 8) * 128 + gn) = v23;
        }
    }
}

// ===========================================================================
// Final fused: per batch element b: h2 = relu(U[n] + 0.2*sum_s V[nb]) built
// into a [128,64] fp16 smem tile, then out[128,16] = h2 @ (Wc_hi + Wc_lo)^T
// via HMMA (split-fp16 wcls == exact fp32 weights). 128 CTAs x 256 thr.
// ===========================================================================
#define FN_OFFA 0
#define FN_OFFB 16384
#define FN_SMEM 20480

__global__ __launch_bounds__(256)
void final_fused(const int* __restrict__ nodes, const int* __restrict__ neigh,
                 float* __restrict__ out) {
    extern __shared__ __align__(1024) char smem[];
    const u32 sb = smem_u32(smem);
    const int tid  = threadIdx.x;
    const int wid  = tid >> 5;
    const int lane = tid & 31;
    const int row0 = blockIdx.x * 128;

    // --- B: wcls hi/lo, 32 rows x 128B, via cp.async ---
    if (tid < 64) {
        int r = tid >> 1, h = tid & 1;
        const __half* src = g_Wc + r * HIDDEN + h * 32;
        u32 bbase = sb + FN_OFFB;
        u32 roff = (u32)r * 128 + (u32)h * 64;
#pragma unroll
        for (int j = 0; j < 4; j++)
            cpasync16(bbase + SW128(roff + j * 16), src + j * 8, 16);
    }
    cpcommit();

    // --- A: gather + aggregate h2 row (2 threads per element) ---
    {
        const int lrow  = tid >> 1;
        const int lhalf = tid & 1;
        const int b = row0 + lrow;               // < 16384 always
        const int n = __ldg(&nodes[b]);

        float val[32];
#pragma unroll
        for (int e = 0; e < 32; e++) val[e] = 0.f;

#pragma unroll
        for (int s = 0; s < NSAMP; s++) {
            int nb = __ldg(&neigh[n * NSAMP + s]);
            const uint4* src = (const uint4*)(g_UV + (size_t)nb * 128 + 64 + lhalf * 32);
#pragma unroll
            for (int j = 0; j < 4; j++) {
                uint4 v = __ldg(src + j);
                u32 w[4] = {v.x, v.y, v.z, v.w};
#pragma unroll
                for (int q = 0; q < 4; q++) {
                    __half2 hh = *(__half2*)&w[q];
                    val[j * 8 + q * 2]     += __low2float(hh);
                    val[j * 8 + q * 2 + 1] += __high2float(hh);
                }
            }
        }
        const uint4* sp = (const uint4*)(g_UV + (size_t)n * 128 + lhalf * 32);
#pragma unroll
        for (int j = 0; j < 4; j++) {
            uint4 v = __ldg(sp + j);
            u32 w[4] = {v.x, v.y, v.z, v.w};
#pragma unroll
            for (int q = 0; q < 4; q++) {
                __half2 hh = *(__half2*)&w[q];
                int e = j * 8 + q * 2;
                val[e]     = fmaxf(fmaf(val[e],     0.2f, __low2float(hh)),  0.f);
                val[e + 1] = fmaxf(fmaf(val[e + 1], 0.2f, __high2float(hh)), 0.f);
            }
        }

        char* abase = smem + FN_OFFA;
        u32 roff = (u32)lrow * 128 + (u32)lhalf * 64;
#pragma unroll
        for (int j = 0; j < 4; j++) {
            __half2 p0 = __floats2half2_rn(val[j * 8 + 0], val[j * 8 + 1]);
            __half2 p1 = __floats2half2_rn(val[j * 8 + 2], val[j * 8 + 3]);
            __half2 p2 = __floats2half2_rn(val[j * 8 + 4], val[j * 8 + 5]);
            __half2 p3 = __floats2half2_rn(val[j * 8 + 6], val[j * 8 + 7]);
            *(uint4*)(abase + SW128(roff + j * 16)) =
                make_uint4(*(u32*)&p0, *(u32*)&p1, *(u32*)&p2, *(u32*)&p3);
        }
    }

    cpwait<0>();
    __syncthreads();

    // --- MMA: warp wid handles rows [wid*16, wid*16+16), all 16 classes ---
    const int grp = lane >> 3, lr = lane & 7;
    const int a_m  = wid * 16 + (grp & 1) * 8 + lr;
    const int a_kb = (grp >> 1) * 16;
    const int b_n  = (grp >> 1) * 8 + lr;          // classes 0..15
    const int b_kb = (grp & 1) * 16;

    float acc[2][4];
#pragma unroll
    for (int i = 0; i < 2; i++)
#pragma unroll
        for (int c = 0; c < 4; c++) acc[i][c] = 0.f;

    u32 sA = sb + FN_OFFA, sB = sb + FN_OFFB;
#pragma unroll
    for (int ks = 0; ks < 4; ks++) {
        u32 a4[4];
        {
            u32 off = SW128((u32)(a_m * 128 + ks * 32 + a_kb));
            ldsm4(a4[0], a4[1], a4[2], a4[3], sA + off);
        }
        u32 bh[2][2], bl[2][2];
        {
            u32 off = SW128((u32)(b_n * 128 + ks * 32 + b_kb));
            u32 r0, r1, r2, r3;
            ldsm4(r0, r1, r2, r3, sB + off);               // wcls hi (rows 0-15)
            bh[0][0] = r0; bh[0][1] = r1; bh[1][0] = r2; bh[1][1] = r3;
            ldsm4(r0, r1, r2, r3, sB + 2048 + off);        // wcls lo (rows 16-31)
            bl[0][0] = r0; bl[0][1] = r1; bl[1][0] = r2; bl[1][1] = r3;
        }
#pragma unroll
        for (int nt = 0; nt < 2; nt++) {
            mma_f16(acc[nt], a4, bh[nt]);
            mma_f16(acc[nt], a4, bl[nt]);
        }
    }

    // epilogue: fp32 out [16384,16]
    const int tm = lane >> 2;
    const int tn = (lane & 3) * 2;
    int gm0 = row0 + wid * 16 + tm;
#pragma unroll
    for (int nt = 0; nt < 2; nt++) {
        int gn = nt * 8 + tn;
        *(float2*)(out + (size_t)gm0 * NCLS + gn)       = make_float2(acc[nt][0], acc[nt][1]);
        *(float2*)(out + (size_t)(gm0 + 8) * NCLS + gn) = make_float2(acc[nt][2], acc[nt][3]);
    }
}

// ---------------------------------------------------------------------------
extern "C" void kernel_launch(void* const* d_in, const int* in_sizes, int n_in,
                              void* d_out, int out_size) {
    const float* features = (const float*)d_in[0];
    const float* w1       = (const float*)d_in[1];
    const float* w2       = (const float*)d_in[2];
    const float* wcls     = (const float*)d_in[3];
    const int*   nodes    = (const int*)d_in[4];
    const int*   neigh    = (const int*)d_in[5];
    float*       out      = (float*)d_out;

    __half *pW1, *pW2, *pPG, *pUV;
    cudaGetSymbolAddress((void**)&pW1, g_W1);
    cudaGetSymbolAddress((void**)&pW2, g_W2);
    cudaGetSymbolAddress((void**)&pPG, g_PG);
    cudaGetSymbolAddress((void**)&pUV, g_UV);

    cudaFuncSetAttribute(gemm1_tc, cudaFuncAttributeMaxDynamicSharedMemorySize, G1_SMEM);
    cudaFuncSetAttribute(gemm2_fused, cudaFuncAttributeMaxDynamicSharedMemorySize, G2_SMEM);
    cudaFuncSetAttribute(final_fused, cudaFuncAttributeMaxDynamicSharedMemorySize, FN_SMEM);

    const int gemm_blocks = (N_NODES + 127) / 128;   // 782

    prep_weights<<<(128 * N_FEATS + 255) / 256, 256>>>(w1, w2, wcls);
    gemm1_tc<<<gemm_blocks, 256, G1_SMEM>>>(features, pW1, pPG, N_NODES);
    gemm2_fused<<<gemm_blocks, 256, G2_SMEM>>>(neigh, pW2, pUV, N_NODES);
    final_fused<<<NBATCH / 128, 256, FN_SMEM>>>(nodes, neigh, out);
}